// round 5
// baseline (speedup 1.0000x reference)
#include <cuda_runtime.h>
#include <cuda_bf16.h>
#include <cstdint>
#include <cfloat>
#include <math.h>

#define NTOK 8192
#define DIMM 512
#define DEPTH 6
#define HEADS 8
#define DH 64
#define WSZ 256
#define INNER 512
#define FF 1365
#define FF2 2730
#define FFPAD 1376          // FF padded to multiple of 32
#define FF2SCR 2816         // FF2 padded to multiple of 128

// ---------------------------------------------------------------------------
// Scratch (device globals; allocation is banned)
// ---------------------------------------------------------------------------
__device__ __align__(256) float g_x[NTOK * DIMM];
__device__ __align__(256) float g_qkv[NTOK * 3 * INNER];
__device__ __align__(256) float g_h[(size_t)NTOK * FF2];
__device__ __align__(256) __nv_bfloat16 g_ah[NTOK * 512],  g_al[NTOK * 512];
__device__ __align__(256) __nv_bfloat16 g_a2h[NTOK * 512], g_a2l[NTOK * 512];
__device__ __align__(256) __nv_bfloat16 g_gh[(size_t)NTOK * FFPAD], g_gl[(size_t)NTOK * FFPAD];
__device__ __align__(256) __nv_bfloat16 g_bh[2176 * 1024], g_bl[2176 * 1024];

__device__ __forceinline__ uint32_t smem_to_u32(const void* p) {
    uint32_t a;
    asm("{ .reg .u64 t; cvta.to.shared.u64 t, %1; cvt.u32.u64 %0, t; }" : "=r"(a) : "l"(p));
    return a;
}
__device__ __forceinline__ void cpasync16(uint32_t dst, const void* src) {
    asm volatile("cp.async.cg.shared.global [%0], [%1], 16;" :: "r"(dst), "l"(src) : "memory");
}
#define CP_COMMIT() asm volatile("cp.async.commit_group;" ::: "memory")
#define CP_WAIT(n) asm volatile("cp.async.wait_group %0;" :: "n"(n) : "memory")

// Swizzled smem layout for bf16 tiles [128 rows][32 k]: two logical rows per
// 128B physical row; 16B chunk index XORed with (physical_row & 7).
__device__ __forceinline__ uint32_t swz(int r, int chunk) {
    int pr = r >> 1;
    int cc = ((r & 1) << 2) | chunk;
    cc ^= (pr & 7);
    return (uint32_t)(pr * 128 + cc * 16);
}

__device__ __forceinline__ void ldx4(uint32_t& d0, uint32_t& d1, uint32_t& d2, uint32_t& d3,
                                     uint32_t addr) {
    asm volatile("ldmatrix.sync.aligned.m8n8.x4.shared.b16 {%0,%1,%2,%3}, [%4];"
                 : "=r"(d0), "=r"(d1), "=r"(d2), "=r"(d3) : "r"(addr));
}
__device__ __forceinline__ void mma16816(float* c, uint32_t a0, uint32_t a1, uint32_t a2,
                                         uint32_t a3, uint32_t b0, uint32_t b1) {
    asm volatile(
        "mma.sync.aligned.m16n8k16.row.col.f32.bf16.bf16.f32 "
        "{%0,%1,%2,%3}, {%4,%5,%6,%7}, {%8,%9}, {%0,%1,%2,%3};"
        : "+f"(c[0]), "+f"(c[1]), "+f"(c[2]), "+f"(c[3])
        : "r"(a0), "r"(a1), "r"(a2), "r"(a3), "r"(b0), "r"(b1));
}

// ===========================================================================
// Conversion kernels: fp32 -> (hi, lo) bf16 split
// ===========================================================================
__global__ void split_pad_A(const float* __restrict__ src,
                            __nv_bfloat16* __restrict__ h, __nv_bfloat16* __restrict__ l,
                            int Mr, int Kc, int Kp)
{
    int idx = blockIdx.x * 256 + threadIdx.x;
    if (idx >= Mr * Kp) return;
    int r = idx / Kp, c = idx - r * Kp;
    float v = (c < Kc) ? src[(size_t)r * Kc + c] : 0.f;
    __nv_bfloat16 hv = __float2bfloat16(v);
    h[idx] = hv;
    l[idx] = __float2bfloat16(v - __bfloat162float(hv));
}

// Weight [K][N] -> transposed, padded splits [Nscr][Kp]
__global__ void split_pad_Bt(const float* __restrict__ src,
                             __nv_bfloat16* __restrict__ h, __nv_bfloat16* __restrict__ l,
                             int Kc, int Nc, int Kp, int Nscr)
{
    int idx = blockIdx.x * 256 + threadIdx.x;
    if (idx >= Nscr * Kp) return;
    int n = idx / Kp, k = idx - n * Kp;
    float v = (n < Nc && k < Kc) ? src[(size_t)k * Nc + n] : 0.f;
    __nv_bfloat16 hv = __float2bfloat16(v);
    h[idx] = hv;
    l[idx] = __float2bfloat16(v - __bfloat162float(hv));
}

// ===========================================================================
// Pure-bf16 tensor-core GEMM:  C(MxN) = A @ B^T  [+bias][+res]; A,B pre-split.
// 128x128x32 tile, 256 threads, 2-stage cp.async pipeline.
// smem stage (32KB): Ah@0, Al@8192, Bh@16384, Bl@24576.
// ===========================================================================
#define STAGE_BYTES 32768
#define GEMM_SMEM (2 * STAGE_BYTES + 1024)

__global__ void __launch_bounds__(256, 2) bf16_gemm_kernel(
    const __nv_bfloat16* __restrict__ Ah, const __nv_bfloat16* __restrict__ Al,
    const __nv_bfloat16* __restrict__ Bh, const __nv_bfloat16* __restrict__ Bl,
    const float* __restrict__ bias, const float* __restrict__ res,
    float* __restrict__ C, __nv_bfloat16* __restrict__ Oh, __nv_bfloat16* __restrict__ Ol,
    int M, int N, int Kpad)
{
    extern __shared__ char smraw[];
    char* sm = (char*)(((uintptr_t)smraw + 1023) & ~(uintptr_t)1023);
    uint32_t sb = smem_to_u32(sm);

    int tid = threadIdx.x, wid = tid >> 5, lane = tid & 31;
    int mw = wid >> 1, nw = wid & 1;
    int m0 = blockIdx.y * 128, n0 = blockIdx.x * 128;

    // ldmatrix lane base addresses (stage 0)
    uint32_t aAddr[2], bAddr[4];
    {
        int t = lane >> 3, l7 = lane & 7;
#pragma unroll
        for (int mi = 0; mi < 2; mi++) {
            int r = mw * 32 + mi * 16 + ((t & 1) << 3) + l7;
            aAddr[mi] = sb + swz(r, t >> 1);
        }
#pragma unroll
        for (int j = 0; j < 4; j++) {
            int r = nw * 64 + j * 16 + ((t >> 1) << 3) + l7;
            bAddr[j] = sb + 16384 + swz(r, t & 1);
        }
    }

    float acc[2][8][4];
#pragma unroll
    for (int mi = 0; mi < 2; mi++)
#pragma unroll
        for (int j = 0; j < 8; j++)
#pragma unroll
            for (int q = 0; q < 4; q++) acc[mi][j][q] = 0.f;

    const int niter = Kpad / 32;

    // copy slots: row cr (0..127), chunk pair c0 = (tid&1)*2
    int cr = tid >> 1;
    int c0 = (tid & 1) * 2;
    const __nv_bfloat16* aSrcH = Ah + (size_t)(m0 + cr) * Kpad + c0 * 8;
    const __nv_bfloat16* aSrcL = Al + (size_t)(m0 + cr) * Kpad + c0 * 8;
    const __nv_bfloat16* bSrcH = Bh + (size_t)(n0 + cr) * Kpad + c0 * 8;
    const __nv_bfloat16* bSrcL = Bl + (size_t)(n0 + cr) * Kpad + c0 * 8;
    uint32_t dA0 = swz(cr, c0), dA1 = swz(cr, c0 + 1);

#define ISSUE_STAGE(s, k0) do {                                           \
        uint32_t base = sb + (s) * STAGE_BYTES;                           \
        cpasync16(base + dA0,         aSrcH + (k0));                      \
        cpasync16(base + dA1,         aSrcH + (k0) + 8);                  \
        cpasync16(base + 8192 + dA0,  aSrcL + (k0));                      \
        cpasync16(base + 8192 + dA1,  aSrcL + (k0) + 8);                  \
        cpasync16(base + 16384 + dA0, bSrcH + (k0));                      \
        cpasync16(base + 16384 + dA1, bSrcH + (k0) + 8);                  \
        cpasync16(base + 24576 + dA0, bSrcL + (k0));                      \
        cpasync16(base + 24576 + dA1, bSrcL + (k0) + 8);                  \
        CP_COMMIT();                                                      \
    } while (0)

    ISSUE_STAGE(0, 0);

    for (int it = 0; it < niter; ++it) {
        int s = it & 1;
        bool more = (it + 1) < niter;
        if (more) ISSUE_STAGE(s ^ 1, (it + 1) * 32);
        if (more) CP_WAIT(1); else CP_WAIT(0);
        __syncthreads();

        uint32_t stage = (uint32_t)s * STAGE_BYTES;
#pragma unroll
        for (int kk = 0; kk < 2; kk++) {
            uint32_t x = (uint32_t)(kk * 32);   // XOR into chunk bits [4:5]
            uint32_t a0A = (aAddr[0] + stage) ^ x;
            uint32_t a1A = (aAddr[1] + stage) ^ x;
            uint32_t ah[2][4], bh[4][4];
            ldx4(ah[0][0], ah[0][1], ah[0][2], ah[0][3], a0A);
            ldx4(ah[1][0], ah[1][1], ah[1][2], ah[1][3], a1A);
#pragma unroll
            for (int j = 0; j < 4; j++) {
                uint32_t bA = (bAddr[j] + stage) ^ x;
                ldx4(bh[j][0], bh[j][1], bh[j][2], bh[j][3], bA);
            }
            // Ah*Bh
#pragma unroll
            for (int mi = 0; mi < 2; mi++)
#pragma unroll
                for (int j = 0; j < 4; j++) {
                    mma16816(acc[mi][2 * j],     ah[mi][0], ah[mi][1], ah[mi][2], ah[mi][3], bh[j][0], bh[j][1]);
                    mma16816(acc[mi][2 * j + 1], ah[mi][0], ah[mi][1], ah[mi][2], ah[mi][3], bh[j][2], bh[j][3]);
                }
            // Ah*Bl
#pragma unroll
            for (int j = 0; j < 4; j++) {
                uint32_t bl[4];
                ldx4(bl[0], bl[1], bl[2], bl[3], ((bAddr[j] + stage) ^ x) + 8192);
#pragma unroll
                for (int mi = 0; mi < 2; mi++) {
                    mma16816(acc[mi][2 * j],     ah[mi][0], ah[mi][1], ah[mi][2], ah[mi][3], bl[0], bl[1]);
                    mma16816(acc[mi][2 * j + 1], ah[mi][0], ah[mi][1], ah[mi][2], ah[mi][3], bl[2], bl[3]);
                }
            }
            // Al*Bh
            ldx4(ah[0][0], ah[0][1], ah[0][2], ah[0][3], a0A + 8192);
            ldx4(ah[1][0], ah[1][1], ah[1][2], ah[1][3], a1A + 8192);
#pragma unroll
            for (int mi = 0; mi < 2; mi++)
#pragma unroll
                for (int j = 0; j < 4; j++) {
                    mma16816(acc[mi][2 * j],     ah[mi][0], ah[mi][1], ah[mi][2], ah[mi][3], bh[j][0], bh[j][1]);
                    mma16816(acc[mi][2 * j + 1], ah[mi][0], ah[mi][1], ah[mi][2], ah[mi][3], bh[j][2], bh[j][3]);
                }
        }
        __syncthreads();
    }
#undef ISSUE_STAGE

    // ---- epilogue: direct STG with fused bias/residual and optional split-out ----
#pragma unroll
    for (int mi = 0; mi < 2; mi++) {
        int rbase = m0 + mw * 32 + mi * 16 + (lane >> 2);
#pragma unroll
        for (int j = 0; j < 8; j++) {
            int col = n0 + nw * 64 + j * 8 + (lane & 3) * 2;
            if (col < N) {
                float bx = 0.f, by = 0.f;
                if (bias) { bx = bias[col]; by = bias[col + 1]; }
#pragma unroll
                for (int half = 0; half < 2; half++) {
                    int r = rbase + half * 8;
                    size_t o = (size_t)r * N + col;
                    float v0 = acc[mi][j][half * 2] + bx;
                    float v1 = acc[mi][j][half * 2 + 1] + by;
                    if (res) { v0 += res[o]; v1 += res[o + 1]; }
                    *(float2*)(C + o) = make_float2(v0, v1);
                    if (Oh) {
                        __nv_bfloat162 hv = __floats2bfloat162_rn(v0, v1);
                        float2 hf = __bfloat1622float2(hv);
                        *(__nv_bfloat162*)(Oh + o) = hv;
                        *(__nv_bfloat162*)(Ol + o) = __floats2bfloat162_rn(v0 - hf.x, v1 - hf.y);
                    }
                }
            }
        }
    }
}

// ---------------------------------------------------------------------------
// QK l2-norm * learned scale + xpos rotary. One warp per (pos, head).
// ---------------------------------------------------------------------------
__global__ void qknorm_rope_kernel(const float* __restrict__ qscale,
                                   const float* __restrict__ kscale)
{
    int task = blockIdx.x * 8 + (threadIdx.x >> 5);
    int lane = threadIdx.x & 31;
    int pos = task >> 3;
    int h = task & 7;

    float* qp = g_qkv + (size_t)pos * (3 * INNER) + h * DH;
    float* kp = qp + INNER;

    float q0 = qp[lane], q1 = qp[lane + 32];
    float k0 = kp[lane], k1 = kp[lane + 32];

    float sq = q0 * q0 + q1 * q1;
    float sk = k0 * k0 + k1 * k1;
#pragma unroll
    for (int o = 16; o > 0; o >>= 1) {
        sq += __shfl_xor_sync(0xFFFFFFFF, sq, o);
        sk += __shfl_xor_sync(0xFFFFFFFF, sk, o);
    }
    float invq = 1.f / fmaxf(sqrtf(sq), 1e-12f);
    float invk = 1.f / fmaxf(sqrtf(sk), 1e-12f);
    q0 *= invq * qscale[lane];
    q1 *= invq * qscale[lane + 32];
    k0 *= invk * kscale[lane];
    k1 *= invk * kscale[lane + 32];

    float t = (float)pos;
    float inv_freq = powf(10000.f, -(float)lane / 32.f);
    float fr = t * inv_freq;
    float c = cosf(fr), s = sinf(fr);
    float sv = (2.f * (float)lane + 0.4f * 64.f) / (1.4f * 64.f);
    float pw = (t - (float)(NTOK / 2)) / (float)(WSZ / 2);
    float xs = powf(sv, pw);
    float ixs = 1.f / xs;

    qp[lane]      = (q0 * c - q1 * s) * xs;
    qp[lane + 32] = (q1 * c + q0 * s) * xs;
    kp[lane]      = (k0 * c - k1 * s) * ixs;
    kp[lane + 32] = (k1 * c + k0 * s) * ixs;
}

// ---------------------------------------------------------------------------
// Local windowed attention; epilogue emits bf16 hi/lo splits directly.
// ---------------------------------------------------------------------------
__global__ void __launch_bounds__(256) local_attn_kernel()
{
    extern __shared__ float smf[];
    float* Ks = smf;
    float* Vs = smf + 256 * 64;

    int w = blockIdx.x;
    int h = blockIdx.y;
    int ti = threadIdx.x;
    int qpos = w * WSZ + ti;

    const float* qp = g_qkv + (size_t)qpos * (3 * INNER) + h * DH;
    float4 q[16];
#pragma unroll
    for (int i = 0; i < 16; i++) q[i] = *(const float4*)(qp + 4 * i);

    float acc[64];
#pragma unroll
    for (int d = 0; d < 64; d++) acc[d] = 0.f;
    float m = -FLT_MAX, l = 0.f;

    int cstart = (w == 0) ? 1 : 0;
    for (int c = cstart; c < 2; c++) {
        __syncthreads();
        int kbase = (w - 1 + c) * WSZ;
#pragma unroll
        for (int i = 0; i < 16; i++) {
            int idx = ti * 16 + i;
            int row = idx >> 4;
            int d4 = (idx & 15) * 4;
            const float* kp = g_qkv + (size_t)(kbase + row) * (3 * INNER) + INNER + h * DH + d4;
            *(float4*)&Ks[row * 64 + d4] = *(const float4*)kp;
            *(float4*)&Vs[row * 64 + d4] = *(const float4*)(kp + INNER);
        }
        __syncthreads();

        if (c == 0) {
            for (int j = 255; j >= ti; j--) {
                const float4* krow = (const float4*)&Ks[j * 64];
                float s = 0.f;
#pragma unroll
                for (int i = 0; i < 16; i++) {
                    float4 kk = krow[i];
                    s += q[i].x * kk.x + q[i].y * kk.y + q[i].z * kk.z + q[i].w * kk.w;
                }
                s *= 8.0f;
                if (s > m) {
                    float sc = expf(m - s);
                    l *= sc;
#pragma unroll
                    for (int d = 0; d < 64; d++) acc[d] *= sc;
                    m = s;
                }
                float p = expf(s - m);
                l += p;
                const float* vrow = &Vs[j * 64];
#pragma unroll
                for (int d = 0; d < 64; d++) acc[d] += p * vrow[d];
            }
        } else {
            for (int j = 0; j <= ti; j++) {
                const float4* krow = (const float4*)&Ks[j * 64];
                float s = 0.f;
#pragma unroll
                for (int i = 0; i < 16; i++) {
                    float4 kk = krow[i];
                    s += q[i].x * kk.x + q[i].y * kk.y + q[i].z * kk.z + q[i].w * kk.w;
                }
                s *= 8.0f;
                if (s > m) {
                    float sc = expf(m - s);
                    l *= sc;
#pragma unroll
                    for (int d = 0; d < 64; d++) acc[d] *= sc;
                    m = s;
                }
                float p = expf(s - m);
                l += p;
                const float* vrow = &Vs[j * 64];
#pragma unroll
                for (int d = 0; d < 64; d++) acc[d] += p * vrow[d];
            }
        }
    }

    float invl = 1.f / l;
    size_t ob = (size_t)qpos * INNER + h * DH;
#pragma unroll
    for (int d = 0; d < 64; d += 2) {
        float v0 = acc[d] * invl, v1 = acc[d + 1] * invl;
        __nv_bfloat162 hv = __floats2bfloat162_rn(v0, v1);
        float2 hf = __bfloat1622float2(hv);
        *(__nv_bfloat162*)(g_ah + ob + d) = hv;
        *(__nv_bfloat162*)(g_al + ob + d) = __floats2bfloat162_rn(v0 - hf.x, v1 - hf.y);
    }
}

// ---------------------------------------------------------------------------
// GLU with exact GELU; emits padded bf16 splits directly.
// ---------------------------------------------------------------------------
__global__ void glu_kernel()
{
    int idx = blockIdx.x * blockDim.x + threadIdx.x;
    if (idx >= NTOK * FFPAD) return;
    int r = idx / FFPAD;
    int jc = idx - r * FFPAD;
    float v = 0.f;
    if (jc < FF) {
        float a = g_h[(size_t)r * FF2 + jc];
        float g = g_h[(size_t)r * FF2 + FF + jc];
        v = a * 0.5f * g * (1.f + erff(g * 0.70710678118654752f));
    }
    __nv_bfloat16 hv = __float2bfloat16(v);
    g_gh[idx] = hv;
    g_gl[idx] = __float2bfloat16(v - __bfloat162float(hv));
}

// ---------------------------------------------------------------------------
extern "C" void kernel_launch(void* const* d_in, const int* in_sizes, int n_in,
                              void* d_out, int out_size)
{
    const float* x      = (const float*)d_in[0];
    const float* Wqkv   = (const float*)d_in[1];
    const float* Wo     = (const float*)d_in[2];
    const float* qscale = (const float*)d_in[3];
    const float* kscale = (const float*)d_in[4];
    const float* W1     = (const float*)d_in[5];
    const float* b1     = (const float*)d_in[6];
    const float* W2     = (const float*)d_in[7];
    const float* b2     = (const float*)d_in[8];

    float *px, *pqkv, *ph;
    __nv_bfloat16 *pah, *pal, *pa2h, *pa2l, *pgh, *pgl, *pbh, *pbl;
    cudaGetSymbolAddress((void**)&px, g_x);
    cudaGetSymbolAddress((void**)&pqkv, g_qkv);
    cudaGetSymbolAddress((void**)&ph, g_h);
    cudaGetSymbolAddress((void**)&pah, g_ah);
    cudaGetSymbolAddress((void**)&pal, g_al);
    cudaGetSymbolAddress((void**)&pa2h, g_a2h);
    cudaGetSymbolAddress((void**)&pa2l, g_a2l);
    cudaGetSymbolAddress((void**)&pgh, g_gh);
    cudaGetSymbolAddress((void**)&pgl, g_gl);
    cudaGetSymbolAddress((void**)&pbh, g_bh);
    cudaGetSymbolAddress((void**)&pbl, g_bl);

    cudaFuncSetAttribute(local_attn_kernel,
                         cudaFuncAttributeMaxDynamicSharedMemorySize, 2 * 256 * 64 * 4);
    cudaFuncSetAttribute(bf16_gemm_kernel,
                         cudaFuncAttributeMaxDynamicSharedMemorySize, GEMM_SMEM);

    // initial activation split: x -> g_ah/g_al
    split_pad_A<<<(NTOK * 512 + 255) / 256, 256>>>(x, pah, pal, NTOK, DIMM, 512);

    for (int lyr = 0; lyr < DEPTH; lyr++) {
        const float* xres = (lyr == 0) ? x : px;

        // 1) QKV projection: A = g_ah (x split), B = Wqkv^T
        split_pad_Bt<<<(1536 * 512 + 255) / 256, 256>>>(
            Wqkv + (size_t)lyr * DIMM * 3 * INNER, pbh, pbl, DIMM, 3 * INNER, 512, 1536);
        bf16_gemm_kernel<<<dim3(12, 64), 256, GEMM_SMEM>>>(
            pah, pal, pbh, pbl, nullptr, nullptr, pqkv, nullptr, nullptr,
            NTOK, 3 * INNER, 512);

        // 2) qk norm + xpos rotary
        qknorm_rope_kernel<<<NTOK, 256>>>(qscale + lyr * DH, kscale + lyr * DH);

        // 3) local attention (writes g_ah/g_al splits)
        local_attn_kernel<<<dim3(NTOK / WSZ, HEADS), 256, 2 * 256 * 64 * 4>>>();

        // 4) output projection + residual; split-out px -> g_a2h/g_a2l
        split_pad_Bt<<<(512 * 512 + 255) / 256, 256>>>(
            Wo + (size_t)lyr * INNER * DIMM, pbh, pbl, INNER, DIMM, 512, 512);
        bf16_gemm_kernel<<<dim3(4, 64), 256, GEMM_SMEM>>>(
            pah, pal, pbh, pbl, nullptr, xres, px, pa2h, pa2l,
            NTOK, DIMM, 512);

        // 5) FF up projection + b1
        split_pad_Bt<<<(FF2SCR * 512 + 255) / 256, 256>>>(
            W1 + (size_t)lyr * DIMM * FF2, pbh, pbl, DIMM, FF2, 512, FF2SCR);
        bf16_gemm_kernel<<<dim3(22, 64), 256, GEMM_SMEM>>>(
            pa2h, pa2l, pbh, pbl, b1 + (size_t)lyr * FF2, nullptr, ph, nullptr, nullptr,
            NTOK, FF2, 512);

        // 6) gated GELU (writes g_gh/g_gl padded splits)
        glu_kernel<<<(NTOK * FFPAD + 255) / 256, 256>>>();

        // 7) FF down projection + b2 + residual; split-out for next layer
        split_pad_Bt<<<(512 * FFPAD + 255) / 256, 256>>>(
            W2 + (size_t)lyr * FF * DIMM, pbh, pbl, FF, DIMM, FFPAD, 512);
        float* outp = (lyr == DEPTH - 1) ? (float*)d_out : px;
        __nv_bfloat16* oh = (lyr == DEPTH - 1) ? nullptr : pah;
        __nv_bfloat16* ol = (lyr == DEPTH - 1) ? nullptr : pal;
        bf16_gemm_kernel<<<dim3(4, 64), 256, GEMM_SMEM>>>(
            pgh, pgl, pbh, pbl, b2 + (size_t)lyr * DIMM, px, outp, oh, ol,
            NTOK, DIMM, FFPAD);
    }
}

// round 6
// speedup vs baseline: 1.6028x; 1.6028x over previous
#include <cuda_runtime.h>
#include <cuda_bf16.h>
#include <cstdint>
#include <cfloat>
#include <math.h>

#define NTOK 8192
#define DIMM 512
#define DEPTH 6
#define HEADS 8
#define DH 64
#define WSZ 256
#define INNER 512
#define FF 1365
#define FF2 2730
#define FFPAD 1376          // FF padded to multiple of 32
#define FF2SCR 2816         // FF2 padded to multiple of 128

// ---------------------------------------------------------------------------
// Scratch (device globals; allocation is banned)
// ---------------------------------------------------------------------------
__device__ __align__(256) float g_x[NTOK * DIMM];
__device__ __align__(256) float g_qkv[NTOK * 3 * INNER];
__device__ __align__(256) float g_h[(size_t)NTOK * FF2];
__device__ __align__(256) __nv_bfloat16 g_ah[NTOK * 512],  g_al[NTOK * 512];
__device__ __align__(256) __nv_bfloat16 g_a2h[NTOK * 512], g_a2l[NTOK * 512];
__device__ __align__(256) __nv_bfloat16 g_gh[(size_t)NTOK * FFPAD], g_gl[(size_t)NTOK * FFPAD];
__device__ __align__(256) __nv_bfloat16 g_bh[2176 * 1024], g_bl[2176 * 1024];

__device__ __forceinline__ uint32_t smem_to_u32(const void* p) {
    uint32_t a;
    asm("{ .reg .u64 t; cvta.to.shared.u64 t, %1; cvt.u32.u64 %0, t; }" : "=r"(a) : "l"(p));
    return a;
}
__device__ __forceinline__ void cpasync16(uint32_t dst, const void* src) {
    asm volatile("cp.async.cg.shared.global [%0], [%1], 16;" :: "r"(dst), "l"(src) : "memory");
}
#define CP_COMMIT() asm volatile("cp.async.commit_group;" ::: "memory")
#define CP_WAIT(n) asm volatile("cp.async.wait_group %0;" :: "n"(n) : "memory")

// Swizzled smem layout for bf16 tiles [128 rows][32 k]: two logical rows per
// 128B physical row; 16B chunk index XORed with (physical_row & 7).
__device__ __forceinline__ uint32_t swz(int r, int chunk) {
    int pr = r >> 1;
    int cc = ((r & 1) << 2) | chunk;
    cc ^= (pr & 7);
    return (uint32_t)(pr * 128 + cc * 16);
}

__device__ __forceinline__ void ldx4(uint32_t& d0, uint32_t& d1, uint32_t& d2, uint32_t& d3,
                                     uint32_t addr) {
    asm volatile("ldmatrix.sync.aligned.m8n8.x4.shared.b16 {%0,%1,%2,%3}, [%4];"
                 : "=r"(d0), "=r"(d1), "=r"(d2), "=r"(d3) : "r"(addr));
}
__device__ __forceinline__ void mma16816(float* c, uint32_t a0, uint32_t a1, uint32_t a2,
                                         uint32_t a3, uint32_t b0, uint32_t b1) {
    asm volatile(
        "mma.sync.aligned.m16n8k16.row.col.f32.bf16.bf16.f32 "
        "{%0,%1,%2,%3}, {%4,%5,%6,%7}, {%8,%9}, {%0,%1,%2,%3};"
        : "+f"(c[0]), "+f"(c[1]), "+f"(c[2]), "+f"(c[3])
        : "r"(a0), "r"(a1), "r"(a2), "r"(a3), "r"(b0), "r"(b1));
}

// ===========================================================================
// Conversion kernels: fp32 -> (hi, lo) bf16 split
// ===========================================================================
__global__ void split_pad_A(const float* __restrict__ src,
                            __nv_bfloat16* __restrict__ h, __nv_bfloat16* __restrict__ l,
                            int Mr, int Kc, int Kp)
{
    int idx = blockIdx.x * 256 + threadIdx.x;
    if (idx >= Mr * Kp) return;
    int r = idx / Kp, c = idx - r * Kp;
    float v = (c < Kc) ? src[(size_t)r * Kc + c] : 0.f;
    __nv_bfloat16 hv = __float2bfloat16(v);
    h[idx] = hv;
    l[idx] = __float2bfloat16(v - __bfloat162float(hv));
}

// Weight [Kc][Nc] -> transposed, padded splits [Nscr][Kp].
// 32x32 smem tile transpose: coalesced reads AND writes, conflict-free.
__global__ void split_pad_Bt(const float* __restrict__ src,
                             __nv_bfloat16* __restrict__ h, __nv_bfloat16* __restrict__ l,
                             int Kc, int Nc, int Kp, int Nscr)
{
    __shared__ float t[32][33];
    int tk0 = blockIdx.x * 32;     // k tile base
    int tn0 = blockIdx.y * 32;     // n tile base
    int tx = threadIdx.x & 31;     // lane
    int ty = threadIdx.x >> 5;     // warp 0..7

#pragma unroll
    for (int i = 0; i < 4; i++) {
        int k = tk0 + ty + 8 * i, n = tn0 + tx;
        float v = (k < Kc && n < Nc) ? src[(size_t)k * Nc + n] : 0.f;
        t[ty + 8 * i][tx] = v;
    }
    __syncthreads();
#pragma unroll
    for (int i = 0; i < 4; i++) {
        int n = tn0 + ty + 8 * i, k = tk0 + tx;
        if (n < Nscr && k < Kp) {
            float v = t[tx][ty + 8 * i];
            __nv_bfloat16 hv = __float2bfloat16(v);
            size_t o = (size_t)n * Kp + k;
            h[o] = hv;
            l[o] = __float2bfloat16(v - __bfloat162float(hv));
        }
    }
}

// ===========================================================================
// Pure-bf16 tensor-core GEMM:  C(MxN) = A @ B^T  [+bias][+res]; A,B pre-split.
// 128x128x32 tile, 256 threads, 3-stage cp.async pipeline.
// smem stage (32KB): Ah@0, Al@8192, Bh@16384, Bl@24576.
// ===========================================================================
#define STAGE_BYTES 32768
#define NSTAGE 3
#define GEMM_SMEM (NSTAGE * STAGE_BYTES + 1024)

__global__ void __launch_bounds__(256, 2) bf16_gemm_kernel(
    const __nv_bfloat16* __restrict__ Ah, const __nv_bfloat16* __restrict__ Al,
    const __nv_bfloat16* __restrict__ Bh, const __nv_bfloat16* __restrict__ Bl,
    const float* __restrict__ bias, const float* __restrict__ res,
    float* __restrict__ C, __nv_bfloat16* __restrict__ Oh, __nv_bfloat16* __restrict__ Ol,
    int M, int N, int Kpad)
{
    extern __shared__ char smraw[];
    char* sm = (char*)(((uintptr_t)smraw + 1023) & ~(uintptr_t)1023);
    uint32_t sb = smem_to_u32(sm);

    int tid = threadIdx.x, wid = tid >> 5, lane = tid & 31;
    int mw = wid >> 1, nw = wid & 1;
    int m0 = blockIdx.y * 128, n0 = blockIdx.x * 128;

    // ldmatrix lane base addresses (stage 0)
    uint32_t aAddr[2], bAddr[4];
    {
        int t = lane >> 3, l7 = lane & 7;
#pragma unroll
        for (int mi = 0; mi < 2; mi++) {
            int r = mw * 32 + mi * 16 + ((t & 1) << 3) + l7;
            aAddr[mi] = sb + swz(r, t >> 1);
        }
#pragma unroll
        for (int j = 0; j < 4; j++) {
            int r = nw * 64 + j * 16 + ((t >> 1) << 3) + l7;
            bAddr[j] = sb + 16384 + swz(r, t & 1);
        }
    }

    float acc[2][8][4];
#pragma unroll
    for (int mi = 0; mi < 2; mi++)
#pragma unroll
        for (int j = 0; j < 8; j++)
#pragma unroll
            for (int q = 0; q < 4; q++) acc[mi][j][q] = 0.f;

    const int niter = Kpad / 32;

    // copy slots: row cr (0..127), chunk pair c0 = (tid&1)*2
    int cr = tid >> 1;
    int c0 = (tid & 1) * 2;
    const __nv_bfloat16* aSrcH = Ah + (size_t)(m0 + cr) * Kpad + c0 * 8;
    const __nv_bfloat16* aSrcL = Al + (size_t)(m0 + cr) * Kpad + c0 * 8;
    const __nv_bfloat16* bSrcH = Bh + (size_t)(n0 + cr) * Kpad + c0 * 8;
    const __nv_bfloat16* bSrcL = Bl + (size_t)(n0 + cr) * Kpad + c0 * 8;
    uint32_t dA0 = swz(cr, c0), dA1 = swz(cr, c0 + 1);

#define ISSUE_STAGE(s, k0) do {                                           \
        uint32_t base = sb + (uint32_t)(s) * STAGE_BYTES;                 \
        cpasync16(base + dA0,         aSrcH + (k0));                      \
        cpasync16(base + dA1,         aSrcH + (k0) + 8);                  \
        cpasync16(base + 8192 + dA0,  aSrcL + (k0));                      \
        cpasync16(base + 8192 + dA1,  aSrcL + (k0) + 8);                  \
        cpasync16(base + 16384 + dA0, bSrcH + (k0));                      \
        cpasync16(base + 16384 + dA1, bSrcH + (k0) + 8);                  \
        cpasync16(base + 24576 + dA0, bSrcL + (k0));                      \
        cpasync16(base + 24576 + dA1, bSrcL + (k0) + 8);                  \
        CP_COMMIT();                                                      \
    } while (0)

    ISSUE_STAGE(0, 0);
    if (niter > 1) ISSUE_STAGE(1, 32);

    for (int it = 0; it < niter; ++it) {
        int s = it % NSTAGE;
        if (it + 2 < niter) {
            ISSUE_STAGE((it + 2) % NSTAGE, (it + 2) * 32);
            CP_WAIT(2);
        } else if (it + 1 < niter) {
            CP_WAIT(1);
        } else {
            CP_WAIT(0);
        }
        __syncthreads();

        uint32_t stage = (uint32_t)s * STAGE_BYTES;
#pragma unroll
        for (int kk = 0; kk < 2; kk++) {
            uint32_t x = (uint32_t)(kk * 32);   // XOR into chunk bits [4:5]
            uint32_t a0A = (aAddr[0] + stage) ^ x;
            uint32_t a1A = (aAddr[1] + stage) ^ x;
            uint32_t ah[2][4], bh[4][4];
            ldx4(ah[0][0], ah[0][1], ah[0][2], ah[0][3], a0A);
            ldx4(ah[1][0], ah[1][1], ah[1][2], ah[1][3], a1A);
#pragma unroll
            for (int j = 0; j < 4; j++) {
                uint32_t bA = (bAddr[j] + stage) ^ x;
                ldx4(bh[j][0], bh[j][1], bh[j][2], bh[j][3], bA);
            }
            // Ah*Bh
#pragma unroll
            for (int mi = 0; mi < 2; mi++)
#pragma unroll
                for (int j = 0; j < 4; j++) {
                    mma16816(acc[mi][2 * j],     ah[mi][0], ah[mi][1], ah[mi][2], ah[mi][3], bh[j][0], bh[j][1]);
                    mma16816(acc[mi][2 * j + 1], ah[mi][0], ah[mi][1], ah[mi][2], ah[mi][3], bh[j][2], bh[j][3]);
                }
            // Ah*Bl
#pragma unroll
            for (int j = 0; j < 4; j++) {
                uint32_t bl[4];
                ldx4(bl[0], bl[1], bl[2], bl[3], ((bAddr[j] + stage) ^ x) + 8192);
#pragma unroll
                for (int mi = 0; mi < 2; mi++) {
                    mma16816(acc[mi][2 * j],     ah[mi][0], ah[mi][1], ah[mi][2], ah[mi][3], bl[0], bl[1]);
                    mma16816(acc[mi][2 * j + 1], ah[mi][0], ah[mi][1], ah[mi][2], ah[mi][3], bl[2], bl[3]);
                }
            }
            // Al*Bh
            ldx4(ah[0][0], ah[0][1], ah[0][2], ah[0][3], a0A + 8192);
            ldx4(ah[1][0], ah[1][1], ah[1][2], ah[1][3], a1A + 8192);
#pragma unroll
            for (int mi = 0; mi < 2; mi++)
#pragma unroll
                for (int j = 0; j < 4; j++) {
                    mma16816(acc[mi][2 * j],     ah[mi][0], ah[mi][1], ah[mi][2], ah[mi][3], bh[j][0], bh[j][1]);
                    mma16816(acc[mi][2 * j + 1], ah[mi][0], ah[mi][1], ah[mi][2], ah[mi][3], bh[j][2], bh[j][3]);
                }
        }
        __syncthreads();
    }
#undef ISSUE_STAGE

    // ---- epilogue: direct STG with fused bias/residual and optional split-out ----
#pragma unroll
    for (int mi = 0; mi < 2; mi++) {
        int rbase = m0 + mw * 32 + mi * 16 + (lane >> 2);
#pragma unroll
        for (int j = 0; j < 8; j++) {
            int col = n0 + nw * 64 + j * 8 + (lane & 3) * 2;
            if (col < N) {
                float bx = 0.f, by = 0.f;
                if (bias) { bx = bias[col]; by = bias[col + 1]; }
#pragma unroll
                for (int half = 0; half < 2; half++) {
                    int r = rbase + half * 8;
                    size_t o = (size_t)r * N + col;
                    float v0 = acc[mi][j][half * 2] + bx;
                    float v1 = acc[mi][j][half * 2 + 1] + by;
                    if (res) { v0 += res[o]; v1 += res[o + 1]; }
                    *(float2*)(C + o) = make_float2(v0, v1);
                    if (Oh) {
                        __nv_bfloat162 hv = __floats2bfloat162_rn(v0, v1);
                        float2 hf = __bfloat1622float2(hv);
                        *(__nv_bfloat162*)(Oh + o) = hv;
                        *(__nv_bfloat162*)(Ol + o) = __floats2bfloat162_rn(v0 - hf.x, v1 - hf.y);
                    }
                }
            }
        }
    }
}

// ---------------------------------------------------------------------------
// QK l2-norm * learned scale + xpos rotary. One warp per (pos, head).
// ---------------------------------------------------------------------------
__global__ void qknorm_rope_kernel(const float* __restrict__ qscale,
                                   const float* __restrict__ kscale)
{
    int task = blockIdx.x * 8 + (threadIdx.x >> 5);
    int lane = threadIdx.x & 31;
    int pos = task >> 3;
    int h = task & 7;

    float* qp = g_qkv + (size_t)pos * (3 * INNER) + h * DH;
    float* kp = qp + INNER;

    float q0 = qp[lane], q1 = qp[lane + 32];
    float k0 = kp[lane], k1 = kp[lane + 32];

    float sq = q0 * q0 + q1 * q1;
    float sk = k0 * k0 + k1 * k1;
#pragma unroll
    for (int o = 16; o > 0; o >>= 1) {
        sq += __shfl_xor_sync(0xFFFFFFFF, sq, o);
        sk += __shfl_xor_sync(0xFFFFFFFF, sk, o);
    }
    float invq = 1.f / fmaxf(sqrtf(sq), 1e-12f);
    float invk = 1.f / fmaxf(sqrtf(sk), 1e-12f);
    q0 *= invq * qscale[lane];
    q1 *= invq * qscale[lane + 32];
    k0 *= invk * kscale[lane];
    k1 *= invk * kscale[lane + 32];

    float t = (float)pos;
    float inv_freq = powf(10000.f, -(float)lane / 32.f);
    float fr = t * inv_freq;
    float c = cosf(fr), s = sinf(fr);
    float sv = (2.f * (float)lane + 0.4f * 64.f) / (1.4f * 64.f);
    float pw = (t - (float)(NTOK / 2)) / (float)(WSZ / 2);
    float xs = powf(sv, pw);
    float ixs = 1.f / xs;

    qp[lane]      = (q0 * c - q1 * s) * xs;
    qp[lane + 32] = (q1 * c + q0 * s) * xs;
    kp[lane]      = (k0 * c - k1 * s) * ixs;
    kp[lane + 32] = (k1 * c + k0 * s) * ixs;
}

// ---------------------------------------------------------------------------
// Local windowed attention; epilogue emits bf16 hi/lo splits directly.
// ---------------------------------------------------------------------------
__global__ void __launch_bounds__(256) local_attn_kernel()
{
    extern __shared__ float smf[];
    float* Ks = smf;
    float* Vs = smf + 256 * 64;

    int w = blockIdx.x;
    int h = blockIdx.y;
    int ti = threadIdx.x;
    int qpos = w * WSZ + ti;

    const float* qp = g_qkv + (size_t)qpos * (3 * INNER) + h * DH;
    float4 q[16];
#pragma unroll
    for (int i = 0; i < 16; i++) q[i] = *(const float4*)(qp + 4 * i);

    float acc[64];
#pragma unroll
    for (int d = 0; d < 64; d++) acc[d] = 0.f;
    float m = -FLT_MAX, l = 0.f;

    int cstart = (w == 0) ? 1 : 0;
    for (int c = cstart; c < 2; c++) {
        __syncthreads();
        int kbase = (w - 1 + c) * WSZ;
#pragma unroll
        for (int i = 0; i < 16; i++) {
            int idx = ti * 16 + i;
            int row = idx >> 4;
            int d4 = (idx & 15) * 4;
            const float* kp = g_qkv + (size_t)(kbase + row) * (3 * INNER) + INNER + h * DH + d4;
            *(float4*)&Ks[row * 64 + d4] = *(const float4*)kp;
            *(float4*)&Vs[row * 64 + d4] = *(const float4*)(kp + INNER);
        }
        __syncthreads();

        if (c == 0) {
            for (int j = 255; j >= ti; j--) {
                const float4* krow = (const float4*)&Ks[j * 64];
                float s = 0.f;
#pragma unroll
                for (int i = 0; i < 16; i++) {
                    float4 kk = krow[i];
                    s += q[i].x * kk.x + q[i].y * kk.y + q[i].z * kk.z + q[i].w * kk.w;
                }
                s *= 8.0f;
                if (s > m) {
                    float sc = __expf(m - s);
                    l *= sc;
#pragma unroll
                    for (int d = 0; d < 64; d++) acc[d] *= sc;
                    m = s;
                }
                float p = __expf(s - m);
                l += p;
                const float* vrow = &Vs[j * 64];
#pragma unroll
                for (int d = 0; d < 64; d++) acc[d] += p * vrow[d];
            }
        } else {
            for (int j = 0; j <= ti; j++) {
                const float4* krow = (const float4*)&Ks[j * 64];
                float s = 0.f;
#pragma unroll
                for (int i = 0; i < 16; i++) {
                    float4 kk = krow[i];
                    s += q[i].x * kk.x + q[i].y * kk.y + q[i].z * kk.z + q[i].w * kk.w;
                }
                s *= 8.0f;
                if (s > m) {
                    float sc = __expf(m - s);
                    l *= sc;
#pragma unroll
                    for (int d = 0; d < 64; d++) acc[d] *= sc;
                    m = s;
                }
                float p = __expf(s - m);
                l += p;
                const float* vrow = &Vs[j * 64];
#pragma unroll
                for (int d = 0; d < 64; d++) acc[d] += p * vrow[d];
            }
        }
    }

    float invl = 1.f / l;
    size_t ob = (size_t)qpos * INNER + h * DH;
#pragma unroll
    for (int d = 0; d < 64; d += 2) {
        float v0 = acc[d] * invl, v1 = acc[d + 1] * invl;
        __nv_bfloat162 hv = __floats2bfloat162_rn(v0, v1);
        float2 hf = __bfloat1622float2(hv);
        *(__nv_bfloat162*)(g_ah + ob + d) = hv;
        *(__nv_bfloat162*)(g_al + ob + d) = __floats2bfloat162_rn(v0 - hf.x, v1 - hf.y);
    }
}

// ---------------------------------------------------------------------------
// GLU with exact GELU; emits padded bf16 splits directly.
// ---------------------------------------------------------------------------
__global__ void glu_kernel()
{
    int idx = blockIdx.x * blockDim.x + threadIdx.x;
    if (idx >= NTOK * FFPAD) return;
    int r = idx / FFPAD;
    int jc = idx - r * FFPAD;
    float v = 0.f;
    if (jc < FF) {
        float a = g_h[(size_t)r * FF2 + jc];
        float g = g_h[(size_t)r * FF2 + FF + jc];
        v = a * 0.5f * g * (1.f + erff(g * 0.70710678118654752f));
    }
    __nv_bfloat16 hv = __float2bfloat16(v);
    g_gh[idx] = hv;
    g_gl[idx] = __float2bfloat16(v - __bfloat162float(hv));
}

// ---------------------------------------------------------------------------
extern "C" void kernel_launch(void* const* d_in, const int* in_sizes, int n_in,
                              void* d_out, int out_size)
{
    const float* x      = (const float*)d_in[0];
    const float* Wqkv   = (const float*)d_in[1];
    const float* Wo     = (const float*)d_in[2];
    const float* qscale = (const float*)d_in[3];
    const float* kscale = (const float*)d_in[4];
    const float* W1     = (const float*)d_in[5];
    const float* b1     = (const float*)d_in[6];
    const float* W2     = (const float*)d_in[7];
    const float* b2     = (const float*)d_in[8];

    float *px, *pqkv, *ph;
    __nv_bfloat16 *pah, *pal, *pa2h, *pa2l, *pgh, *pgl, *pbh, *pbl;
    cudaGetSymbolAddress((void**)&px, g_x);
    cudaGetSymbolAddress((void**)&pqkv, g_qkv);
    cudaGetSymbolAddress((void**)&ph, g_h);
    cudaGetSymbolAddress((void**)&pah, g_ah);
    cudaGetSymbolAddress((void**)&pal, g_al);
    cudaGetSymbolAddress((void**)&pa2h, g_a2h);
    cudaGetSymbolAddress((void**)&pa2l, g_a2l);
    cudaGetSymbolAddress((void**)&pgh, g_gh);
    cudaGetSymbolAddress((void**)&pgl, g_gl);
    cudaGetSymbolAddress((void**)&pbh, g_bh);
    cudaGetSymbolAddress((void**)&pbl, g_bl);

    cudaFuncSetAttribute(local_attn_kernel,
                         cudaFuncAttributeMaxDynamicSharedMemorySize, 2 * 256 * 64 * 4);
    cudaFuncSetAttribute(bf16_gemm_kernel,
                         cudaFuncAttributeMaxDynamicSharedMemorySize, GEMM_SMEM);

    // initial activation split: x -> g_ah/g_al
    split_pad_A<<<(NTOK * 512 + 255) / 256, 256>>>(x, pah, pal, NTOK, DIMM, 512);

    for (int lyr = 0; lyr < DEPTH; lyr++) {
        const float* xres = (lyr == 0) ? x : px;

        // 1) QKV projection: A = g_ah (x split), B = Wqkv^T
        split_pad_Bt<<<dim3(16, 48), 256>>>(
            Wqkv + (size_t)lyr * DIMM * 3 * INNER, pbh, pbl, DIMM, 3 * INNER, 512, 1536);
        bf16_gemm_kernel<<<dim3(12, 64), 256, GEMM_SMEM>>>(
            pah, pal, pbh, pbl, nullptr, nullptr, pqkv, nullptr, nullptr,
            NTOK, 3 * INNER, 512);

        // 2) qk norm + xpos rotary
        qknorm_rope_kernel<<<NTOK, 256>>>(qscale + lyr * DH, kscale + lyr * DH);

        // 3) local attention (writes g_ah/g_al splits)
        local_attn_kernel<<<dim3(NTOK / WSZ, HEADS), 256, 2 * 256 * 64 * 4>>>();

        // 4) output projection + residual; split-out px -> g_a2h/g_a2l
        split_pad_Bt<<<dim3(16, 16), 256>>>(
            Wo + (size_t)lyr * INNER * DIMM, pbh, pbl, INNER, DIMM, 512, 512);
        bf16_gemm_kernel<<<dim3(4, 64), 256, GEMM_SMEM>>>(
            pah, pal, pbh, pbl, nullptr, xres, px, pa2h, pa2l,
            NTOK, DIMM, 512);

        // 5) FF up projection + b1
        split_pad_Bt<<<dim3(16, 88), 256>>>(
            W1 + (size_t)lyr * DIMM * FF2, pbh, pbl, DIMM, FF2, 512, FF2SCR);
        bf16_gemm_kernel<<<dim3(22, 64), 256, GEMM_SMEM>>>(
            pa2h, pa2l, pbh, pbl, b1 + (size_t)lyr * FF2, nullptr, ph, nullptr, nullptr,
            NTOK, FF2, 512);

        // 6) gated GELU (writes g_gh/g_gl padded splits)
        glu_kernel<<<(NTOK * FFPAD + 255) / 256, 256>>>();

        // 7) FF down projection + b2 + residual; split-out for next layer
        split_pad_Bt<<<dim3(43, 16), 256>>>(
            W2 + (size_t)lyr * FF * DIMM, pbh, pbl, FF, DIMM, FFPAD, 512);
        float* outp = (lyr == DEPTH - 1) ? (float*)d_out : px;
        __nv_bfloat16* oh = (lyr == DEPTH - 1) ? nullptr : pah;
        __nv_bfloat16* ol = (lyr == DEPTH - 1) ? nullptr : pal;
        bf16_gemm_kernel<<<dim3(4, 64), 256, GEMM_SMEM>>>(
            pgh, pgl, pbh, pbl, b2 + (size_t)lyr * DIMM, px, outp, oh, ol,
            NTOK, DIMM, FFPAD);
    }
}

// round 7
// speedup vs baseline: 2.1338x; 1.3313x over previous
#include <cuda_runtime.h>
#include <cuda_bf16.h>
#include <cstdint>
#include <cfloat>
#include <math.h>

#define NTOK 8192
#define DIMM 512
#define DEPTH 6
#define HEADS 8
#define DH 64
#define WSZ 256
#define INNER 512
#define FF 1365
#define FF2 2730
#define FFPAD 1376
#define FF2SCR 2816

// ---------------------------------------------------------------------------
// Scratch (device globals; allocation is banned)
// ---------------------------------------------------------------------------
__device__ __align__(256) float g_x[NTOK * DIMM];
__device__ __align__(256) float g_qkv[NTOK * 3 * INNER];
__device__ __align__(256) float g_h[(size_t)NTOK * FF2];
__device__ __align__(256) __nv_bfloat16 g_ah[NTOK * 512],  g_al[NTOK * 512];
__device__ __align__(256) __nv_bfloat16 g_a2h[NTOK * 512], g_a2l[NTOK * 512];
__device__ __align__(256) __nv_bfloat16 g_gh[(size_t)NTOK * FFPAD], g_gl[(size_t)NTOK * FFPAD];
__device__ __align__(256) __nv_bfloat16 g_bh[2176 * 1024], g_bl[2176 * 1024];
// attention operand splits
__device__ __align__(256) __nv_bfloat16 g_qh[NTOK * 512], g_ql[NTOK * 512];
__device__ __align__(256) __nv_bfloat16 g_kh[NTOK * 512], g_kl[NTOK * 512];
__device__ __align__(256) __nv_bfloat16 g_vth[512 * NTOK], g_vtl[512 * NTOK];

__device__ __forceinline__ uint32_t smem_to_u32(const void* p) {
    uint32_t a;
    asm("{ .reg .u64 t; cvta.to.shared.u64 t, %1; cvt.u32.u64 %0, t; }" : "=r"(a) : "l"(p));
    return a;
}
__device__ __forceinline__ void cpasync16(uint32_t dst, const void* src) {
    asm volatile("cp.async.cg.shared.global [%0], [%1], 16;" :: "r"(dst), "l"(src) : "memory");
}
#define CP_COMMIT() asm volatile("cp.async.commit_group;" ::: "memory")
#define CP_WAIT(n) asm volatile("cp.async.wait_group %0;" :: "n"(n) : "memory")

// GEMM tile swizzle: [128 rows][32 k] bf16, 2 logical rows per 128B row.
__device__ __forceinline__ uint32_t swz(int r, int chunk) {
    int pr = r >> 1;
    int cc = ((r & 1) << 2) | chunk;
    cc ^= (pr & 7);
    return (uint32_t)(pr * 128 + cc * 16);
}
// Attention tile swizzle: [rows][64 bf16] = 128B per row, 8 chunks of 16B.
__device__ __forceinline__ uint32_t swz64(int r, int c) {
    return (uint32_t)(r * 128 + ((c ^ (r & 7)) * 16));
}

__device__ __forceinline__ void ldx4(uint32_t& d0, uint32_t& d1, uint32_t& d2, uint32_t& d3,
                                     uint32_t addr) {
    asm volatile("ldmatrix.sync.aligned.m8n8.x4.shared.b16 {%0,%1,%2,%3}, [%4];"
                 : "=r"(d0), "=r"(d1), "=r"(d2), "=r"(d3) : "r"(addr));
}
__device__ __forceinline__ void mma16816(float* c, uint32_t a0, uint32_t a1, uint32_t a2,
                                         uint32_t a3, uint32_t b0, uint32_t b1) {
    asm volatile(
        "mma.sync.aligned.m16n8k16.row.col.f32.bf16.bf16.f32 "
        "{%0,%1,%2,%3}, {%4,%5,%6,%7}, {%8,%9}, {%0,%1,%2,%3};"
        : "+f"(c[0]), "+f"(c[1]), "+f"(c[2]), "+f"(c[3])
        : "r"(a0), "r"(a1), "r"(a2), "r"(a3), "r"(b0), "r"(b1));
}
__device__ __forceinline__ uint32_t packbf2(float a, float b) {
    __nv_bfloat162 h = __floats2bfloat162_rn(a, b);
    return *reinterpret_cast<uint32_t*>(&h);
}

// ===========================================================================
// Conversion kernels
// ===========================================================================
__global__ void split_pad_A(const float* __restrict__ src,
                            __nv_bfloat16* __restrict__ h, __nv_bfloat16* __restrict__ l,
                            int Mr, int Kc, int Kp)
{
    int idx = blockIdx.x * 256 + threadIdx.x;
    if (idx >= Mr * Kp) return;
    int r = idx / Kp, c = idx - r * Kp;
    float v = (c < Kc) ? src[(size_t)r * Kc + c] : 0.f;
    __nv_bfloat16 hv = __float2bfloat16(v);
    h[idx] = hv;
    l[idx] = __float2bfloat16(v - __bfloat162float(hv));
}

// Weight [Kc][Nc] -> transposed, padded splits [Nscr][Kp] (32x32 tiles).
__global__ void split_pad_Bt(const float* __restrict__ src,
                             __nv_bfloat16* __restrict__ h, __nv_bfloat16* __restrict__ l,
                             int Kc, int Nc, int Kp, int Nscr)
{
    __shared__ float t[32][33];
    int tk0 = blockIdx.x * 32;
    int tn0 = blockIdx.y * 32;
    int tx = threadIdx.x & 31;
    int ty = threadIdx.x >> 5;

#pragma unroll
    for (int i = 0; i < 4; i++) {
        int k = tk0 + ty + 8 * i, n = tn0 + tx;
        float v = (k < Kc && n < Nc) ? src[(size_t)k * Nc + n] : 0.f;
        t[ty + 8 * i][tx] = v;
    }
    __syncthreads();
#pragma unroll
    for (int i = 0; i < 4; i++) {
        int n = tn0 + ty + 8 * i, k = tk0 + tx;
        if (n < Nscr && k < Kp) {
            float v = t[tx][ty + 8 * i];
            __nv_bfloat16 hv = __float2bfloat16(v);
            size_t o = (size_t)n * Kp + k;
            h[o] = hv;
            l[o] = __float2bfloat16(v - __bfloat162float(hv));
        }
    }
}

// V transpose+split: g_qkv v-part [tok][hd] (stride 1536, offset 1024)
// -> g_vth/g_vtl [hd][tok]
__global__ void vtrans_kernel()
{
    __shared__ float t[32][33];
    int tok0 = blockIdx.x * 32;
    int hd0 = blockIdx.y * 32;
    int tx = threadIdx.x & 31;
    int ty = threadIdx.x >> 5;
#pragma unroll
    for (int i = 0; i < 4; i++) {
        int tok = tok0 + ty + 8 * i;
        t[ty + 8 * i][tx] = g_qkv[(size_t)tok * 1536 + 1024 + hd0 + tx];
    }
    __syncthreads();
#pragma unroll
    for (int i = 0; i < 4; i++) {
        int hd = hd0 + ty + 8 * i, tok = tok0 + tx;
        float v = t[tx][ty + 8 * i];
        __nv_bfloat16 hv = __float2bfloat16(v);
        size_t o = (size_t)hd * NTOK + tok;
        g_vth[o] = hv;
        g_vtl[o] = __float2bfloat16(v - __bfloat162float(hv));
    }
}

// ===========================================================================
// Pure-bf16 tensor-core GEMM (unchanged from R6)
// ===========================================================================
#define STAGE_BYTES 32768
#define NSTAGE 3
#define GEMM_SMEM (NSTAGE * STAGE_BYTES + 1024)

__global__ void __launch_bounds__(256, 2) bf16_gemm_kernel(
    const __nv_bfloat16* __restrict__ Ah, const __nv_bfloat16* __restrict__ Al,
    const __nv_bfloat16* __restrict__ Bh, const __nv_bfloat16* __restrict__ Bl,
    const float* __restrict__ bias, const float* __restrict__ res,
    float* __restrict__ C, __nv_bfloat16* __restrict__ Oh, __nv_bfloat16* __restrict__ Ol,
    int M, int N, int Kpad)
{
    extern __shared__ char smraw[];
    char* sm = (char*)(((uintptr_t)smraw + 1023) & ~(uintptr_t)1023);
    uint32_t sb = smem_to_u32(sm);

    int tid = threadIdx.x, wid = tid >> 5, lane = tid & 31;
    int mw = wid >> 1, nw = wid & 1;
    int m0 = blockIdx.y * 128, n0 = blockIdx.x * 128;

    uint32_t aAddr[2], bAddr[4];
    {
        int t = lane >> 3, l7 = lane & 7;
#pragma unroll
        for (int mi = 0; mi < 2; mi++) {
            int r = mw * 32 + mi * 16 + ((t & 1) << 3) + l7;
            aAddr[mi] = sb + swz(r, t >> 1);
        }
#pragma unroll
        for (int j = 0; j < 4; j++) {
            int r = nw * 64 + j * 16 + ((t >> 1) << 3) + l7;
            bAddr[j] = sb + 16384 + swz(r, t & 1);
        }
    }

    float acc[2][8][4];
#pragma unroll
    for (int mi = 0; mi < 2; mi++)
#pragma unroll
        for (int j = 0; j < 8; j++)
#pragma unroll
            for (int q = 0; q < 4; q++) acc[mi][j][q] = 0.f;

    const int niter = Kpad / 32;
    int cr = tid >> 1;
    int c0 = (tid & 1) * 2;
    const __nv_bfloat16* aSrcH = Ah + (size_t)(m0 + cr) * Kpad + c0 * 8;
    const __nv_bfloat16* aSrcL = Al + (size_t)(m0 + cr) * Kpad + c0 * 8;
    const __nv_bfloat16* bSrcH = Bh + (size_t)(n0 + cr) * Kpad + c0 * 8;
    const __nv_bfloat16* bSrcL = Bl + (size_t)(n0 + cr) * Kpad + c0 * 8;
    uint32_t dA0 = swz(cr, c0), dA1 = swz(cr, c0 + 1);

#define ISSUE_STAGE(s, k0) do {                                           \
        uint32_t base = sb + (uint32_t)(s) * STAGE_BYTES;                 \
        cpasync16(base + dA0,         aSrcH + (k0));                      \
        cpasync16(base + dA1,         aSrcH + (k0) + 8);                  \
        cpasync16(base + 8192 + dA0,  aSrcL + (k0));                      \
        cpasync16(base + 8192 + dA1,  aSrcL + (k0) + 8);                  \
        cpasync16(base + 16384 + dA0, bSrcH + (k0));                      \
        cpasync16(base + 16384 + dA1, bSrcH + (k0) + 8);                  \
        cpasync16(base + 24576 + dA0, bSrcL + (k0));                      \
        cpasync16(base + 24576 + dA1, bSrcL + (k0) + 8);                  \
        CP_COMMIT();                                                      \
    } while (0)

    ISSUE_STAGE(0, 0);
    if (niter > 1) ISSUE_STAGE(1, 32);

    for (int it = 0; it < niter; ++it) {
        int s = it % NSTAGE;
        if (it + 2 < niter) {
            ISSUE_STAGE((it + 2) % NSTAGE, (it + 2) * 32);
            CP_WAIT(2);
        } else if (it + 1 < niter) {
            CP_WAIT(1);
        } else {
            CP_WAIT(0);
        }
        __syncthreads();

        uint32_t stage = (uint32_t)s * STAGE_BYTES;
#pragma unroll
        for (int kk = 0; kk < 2; kk++) {
            uint32_t x = (uint32_t)(kk * 32);
            uint32_t a0A = (aAddr[0] + stage) ^ x;
            uint32_t a1A = (aAddr[1] + stage) ^ x;
            uint32_t ah[2][4], bh[4][4];
            ldx4(ah[0][0], ah[0][1], ah[0][2], ah[0][3], a0A);
            ldx4(ah[1][0], ah[1][1], ah[1][2], ah[1][3], a1A);
#pragma unroll
            for (int j = 0; j < 4; j++) {
                uint32_t bA = (bAddr[j] + stage) ^ x;
                ldx4(bh[j][0], bh[j][1], bh[j][2], bh[j][3], bA);
            }
#pragma unroll
            for (int mi = 0; mi < 2; mi++)
#pragma unroll
                for (int j = 0; j < 4; j++) {
                    mma16816(acc[mi][2 * j],     ah[mi][0], ah[mi][1], ah[mi][2], ah[mi][3], bh[j][0], bh[j][1]);
                    mma16816(acc[mi][2 * j + 1], ah[mi][0], ah[mi][1], ah[mi][2], ah[mi][3], bh[j][2], bh[j][3]);
                }
#pragma unroll
            for (int j = 0; j < 4; j++) {
                uint32_t bl[4];
                ldx4(bl[0], bl[1], bl[2], bl[3], ((bAddr[j] + stage) ^ x) + 8192);
#pragma unroll
                for (int mi = 0; mi < 2; mi++) {
                    mma16816(acc[mi][2 * j],     ah[mi][0], ah[mi][1], ah[mi][2], ah[mi][3], bl[0], bl[1]);
                    mma16816(acc[mi][2 * j + 1], ah[mi][0], ah[mi][1], ah[mi][2], ah[mi][3], bl[2], bl[3]);
                }
            }
            ldx4(ah[0][0], ah[0][1], ah[0][2], ah[0][3], a0A + 8192);
            ldx4(ah[1][0], ah[1][1], ah[1][2], ah[1][3], a1A + 8192);
#pragma unroll
            for (int mi = 0; mi < 2; mi++)
#pragma unroll
                for (int j = 0; j < 4; j++) {
                    mma16816(acc[mi][2 * j],     ah[mi][0], ah[mi][1], ah[mi][2], ah[mi][3], bh[j][0], bh[j][1]);
                    mma16816(acc[mi][2 * j + 1], ah[mi][0], ah[mi][1], ah[mi][2], ah[mi][3], bh[j][2], bh[j][3]);
                }
        }
        __syncthreads();
    }
#undef ISSUE_STAGE

#pragma unroll
    for (int mi = 0; mi < 2; mi++) {
        int rbase = m0 + mw * 32 + mi * 16 + (lane >> 2);
#pragma unroll
        for (int j = 0; j < 8; j++) {
            int col = n0 + nw * 64 + j * 8 + (lane & 3) * 2;
            if (col < N) {
                float bx = 0.f, by = 0.f;
                if (bias) { bx = bias[col]; by = bias[col + 1]; }
#pragma unroll
                for (int half = 0; half < 2; half++) {
                    int r = rbase + half * 8;
                    size_t o = (size_t)r * N + col;
                    float v0 = acc[mi][j][half * 2] + bx;
                    float v1 = acc[mi][j][half * 2 + 1] + by;
                    if (res) { v0 += res[o]; v1 += res[o + 1]; }
                    *(float2*)(C + o) = make_float2(v0, v1);
                    if (Oh) {
                        __nv_bfloat162 hv = __floats2bfloat162_rn(v0, v1);
                        float2 hf = __bfloat1622float2(hv);
                        *(__nv_bfloat162*)(Oh + o) = hv;
                        *(__nv_bfloat162*)(Ol + o) = __floats2bfloat162_rn(v0 - hf.x, v1 - hf.y);
                    }
                }
            }
        }
    }
}

// ---------------------------------------------------------------------------
// QK l2-norm + xpos rotary; emits bf16 hi/lo splits of q,k.
// ---------------------------------------------------------------------------
__global__ void qknorm_rope_kernel(const float* __restrict__ qscale,
                                   const float* __restrict__ kscale)
{
    int task = blockIdx.x * 8 + (threadIdx.x >> 5);
    int lane = threadIdx.x & 31;
    int pos = task >> 3;
    int h = task & 7;

    const float* qp = g_qkv + (size_t)pos * (3 * INNER) + h * DH;
    const float* kp = qp + INNER;

    float q0 = qp[lane], q1 = qp[lane + 32];
    float k0 = kp[lane], k1 = kp[lane + 32];

    float sq = q0 * q0 + q1 * q1;
    float sk = k0 * k0 + k1 * k1;
#pragma unroll
    for (int o = 16; o > 0; o >>= 1) {
        sq += __shfl_xor_sync(0xFFFFFFFF, sq, o);
        sk += __shfl_xor_sync(0xFFFFFFFF, sk, o);
    }
    float invq = 1.f / fmaxf(sqrtf(sq), 1e-12f);
    float invk = 1.f / fmaxf(sqrtf(sk), 1e-12f);
    q0 *= invq * qscale[lane];
    q1 *= invq * qscale[lane + 32];
    k0 *= invk * kscale[lane];
    k1 *= invk * kscale[lane + 32];

    float t = (float)pos;
    float inv_freq = powf(10000.f, -(float)lane / 32.f);
    float fr = t * inv_freq;
    float c = cosf(fr), s = sinf(fr);
    float sv = (2.f * (float)lane + 0.4f * 64.f) / (1.4f * 64.f);
    float pw = (t - (float)(NTOK / 2)) / (float)(WSZ / 2);
    float xs = powf(sv, pw);
    float ixs = 1.f / xs;

    float qa = (q0 * c - q1 * s) * xs;
    float qb = (q1 * c + q0 * s) * xs;
    float ka = (k0 * c - k1 * s) * ixs;
    float kb = (k1 * c + k0 * s) * ixs;

    size_t ob = (size_t)pos * 512 + h * DH;
    __nv_bfloat16 hv;
    hv = __float2bfloat16(qa); g_qh[ob + lane] = hv;
    g_ql[ob + lane] = __float2bfloat16(qa - __bfloat162float(hv));
    hv = __float2bfloat16(qb); g_qh[ob + lane + 32] = hv;
    g_ql[ob + lane + 32] = __float2bfloat16(qb - __bfloat162float(hv));
    hv = __float2bfloat16(ka); g_kh[ob + lane] = hv;
    g_kl[ob + lane] = __float2bfloat16(ka - __bfloat162float(hv));
    hv = __float2bfloat16(kb); g_kh[ob + lane + 32] = hv;
    g_kl[ob + lane + 32] = __float2bfloat16(kb - __bfloat162float(hv));
}

// ===========================================================================
// Tensor-core flash attention.
// Block = (q-block of 128 rows, head). 256 threads, 8 warps x 16 q-rows.
// Key chunks of 64, double-buffered cp.async. S and PV via bf16x3-split mma.
// smem: Qh@0 (16KB), Ql@16384, stages@32768: each {Kh,Kl,Vth,Vtl} x 8KB.
// ===========================================================================
#define ATT_SMEM (32768 + 2 * 32768 + 1024)

__global__ void __launch_bounds__(256) flash_attn_kernel()
{
    extern __shared__ char smraw[];
    char* sm = (char*)(((uintptr_t)smraw + 1023) & ~(uintptr_t)1023);
    uint32_t sb = smem_to_u32(sm);

    int tid = threadIdx.x, wid = tid >> 5, lane = tid & 31;
    int qb = blockIdx.x;           // 0..63
    int h = blockIdx.y;            // 0..7
    int start = (qb - 2) * 128;    // first key of 6x64 chunk range
    int cBeg = (start < 0) ? (-start) / 64 : 0;

    // ---- prologue: issue Q + first chunk (one group), then chunk+1 ----
    {
#pragma unroll
        for (int i = 0; i < 4; i++) {
            int slot = tid * 4 + i;           // 0..1023
            int row = slot >> 3, ch = slot & 7;
            uint32_t d = swz64(row, ch);
            const __nv_bfloat16* sh = g_qh + (size_t)(qb * 128 + row) * 512 + h * 64 + ch * 8;
            const __nv_bfloat16* slo = g_ql + (size_t)(qb * 128 + row) * 512 + h * 64 + ch * 8;
            cpasync16(sb + d, sh);
            cpasync16(sb + 16384 + d, slo);
        }
        // chunk cBeg into stage 0 (same group as Q)
        int kb = start + cBeg * 64;
        uint32_t base = sb + 32768;
#pragma unroll
        for (int i = 0; i < 2; i++) {
            int slot = tid * 2 + i;
            int row = slot >> 3, ch = slot & 7;
            uint32_t d = swz64(row, ch);
            cpasync16(base + d,         g_kh + (size_t)(kb + row) * 512 + h * 64 + ch * 8);
            cpasync16(base + 8192 + d,  g_kl + (size_t)(kb + row) * 512 + h * 64 + ch * 8);
            cpasync16(base + 16384 + d, g_vth + (size_t)(h * 64 + row) * NTOK + kb + ch * 8);
            cpasync16(base + 24576 + d, g_vtl + (size_t)(h * 64 + row) * NTOK + kb + ch * 8);
        }
        CP_COMMIT();
        if (cBeg + 1 <= 5) {
            int kb2 = start + (cBeg + 1) * 64;
            uint32_t base2 = sb + 32768 + 32768;
#pragma unroll
            for (int i = 0; i < 2; i++) {
                int slot = tid * 2 + i;
                int row = slot >> 3, ch = slot & 7;
                uint32_t d = swz64(row, ch);
                cpasync16(base2 + d,         g_kh + (size_t)(kb2 + row) * 512 + h * 64 + ch * 8);
                cpasync16(base2 + 8192 + d,  g_kl + (size_t)(kb2 + row) * 512 + h * 64 + ch * 8);
                cpasync16(base2 + 16384 + d, g_vth + (size_t)(h * 64 + row) * NTOK + kb2 + ch * 8);
                cpasync16(base2 + 24576 + d, g_vtl + (size_t)(h * 64 + row) * NTOK + kb2 + ch * 8);
            }
            CP_COMMIT();
        }
    }

    int t = lane >> 3, l7 = lane & 7;
    // lane-relative frag offsets (A from Q / P; B from K / Vt)
    uint32_t aOff = swz64(wid * 16 + ((t & 1) << 3) + l7, t >> 1);
    uint32_t bOff[4];
#pragma unroll
    for (int j = 0; j < 4; j++)
        bOff[j] = swz64(j * 16 + ((t >> 1) << 3) + l7, t & 1);

    uint32_t qfh[4][4], qfl[4][4];
    float o4[8][4];
#pragma unroll
    for (int j = 0; j < 8; j++)
#pragma unroll
        for (int q = 0; q < 4; q++) o4[j][q] = 0.f;
    float m0 = -16.f, m1 = -16.f, l0 = 0.f, l1 = 0.f;

    int r0 = qb * 128 + wid * 16 + (lane >> 2);   // tq for c0,c1 rows (+8 for c2,c3)
    int colq = (lane & 3) * 2;

    for (int c = cBeg; c <= 5; c++) {
        int s = (c - cBeg) & 1;
        int kb = start + c * 64;
        if (c < 5) CP_WAIT(1); else CP_WAIT(0);
        __syncthreads();

        if (c == cBeg) {
            // load Q fragments once
#pragma unroll
            for (int ks = 0; ks < 4; ks++) {
                uint32_t x = (uint32_t)(ks * 32);
                ldx4(qfh[ks][0], qfh[ks][1], qfh[ks][2], qfh[ks][3], (sb + aOff) ^ x);
                ldx4(qfl[ks][0], qfl[ks][1], qfl[ks][2], qfl[ks][3], (sb + 16384 + aOff) ^ x);
            }
        }

        uint32_t kvb = sb + 32768 + (uint32_t)s * 32768;

        // ---- S = Q K^T (bf16x3) ----
        float s4[8][4];
#pragma unroll
        for (int j = 0; j < 8; j++)
#pragma unroll
            for (int q = 0; q < 4; q++) s4[j][q] = 0.f;

#pragma unroll
        for (int ks = 0; ks < 4; ks++) {
            uint32_t x = (uint32_t)(ks * 32);
            uint32_t bh[4][4], bl[4][4];
#pragma unroll
            for (int j = 0; j < 4; j++) {
                ldx4(bh[j][0], bh[j][1], bh[j][2], bh[j][3], (kvb + bOff[j]) ^ x);
                ldx4(bl[j][0], bl[j][1], bl[j][2], bl[j][3], (kvb + 8192 + bOff[j]) ^ x);
            }
#pragma unroll
            for (int j = 0; j < 4; j++) {
                mma16816(s4[2 * j],     qfh[ks][0], qfh[ks][1], qfh[ks][2], qfh[ks][3], bh[j][0], bh[j][1]);
                mma16816(s4[2 * j + 1], qfh[ks][0], qfh[ks][1], qfh[ks][2], qfh[ks][3], bh[j][2], bh[j][3]);
                mma16816(s4[2 * j],     qfh[ks][0], qfh[ks][1], qfh[ks][2], qfh[ks][3], bl[j][0], bl[j][1]);
                mma16816(s4[2 * j + 1], qfh[ks][0], qfh[ks][1], qfh[ks][2], qfh[ks][3], bl[j][2], bl[j][3]);
                mma16816(s4[2 * j],     qfl[ks][0], qfl[ks][1], qfl[ks][2], qfl[ks][3], bh[j][0], bh[j][1]);
                mma16816(s4[2 * j + 1], qfl[ks][0], qfl[ks][1], qfl[ks][2], qfl[ks][3], bh[j][2], bh[j][3]);
            }
        }

        // ---- mask + scale ----
#pragma unroll
        for (int j = 0; j < 8; j++) {
            int tkb = kb + j * 8 + colq;
#pragma unroll
            for (int q = 0; q < 4; q++) {
                int tq = r0 + ((q >> 1) << 3);
                int tk = tkb + (q & 1);
                int diff = tq - tk;
                s4[j][q] = (diff >= 0 && diff <= WSZ) ? s4[j][q] * 8.0f : -1e30f;
            }
        }
        // ---- online softmax ----
        float mx0 = -1e30f, mx1 = -1e30f;
#pragma unroll
        for (int j = 0; j < 8; j++) {
            mx0 = fmaxf(mx0, fmaxf(s4[j][0], s4[j][1]));
            mx1 = fmaxf(mx1, fmaxf(s4[j][2], s4[j][3]));
        }
        mx0 = fmaxf(mx0, __shfl_xor_sync(0xFFFFFFFF, mx0, 1));
        mx0 = fmaxf(mx0, __shfl_xor_sync(0xFFFFFFFF, mx0, 2));
        mx1 = fmaxf(mx1, __shfl_xor_sync(0xFFFFFFFF, mx1, 1));
        mx1 = fmaxf(mx1, __shfl_xor_sync(0xFFFFFFFF, mx1, 2));
        float mn0 = fmaxf(m0, mx0), mn1 = fmaxf(m1, mx1);
        float sc0 = __expf(m0 - mn0), sc1 = __expf(m1 - mn1);
        l0 *= sc0; l1 *= sc1;
#pragma unroll
        for (int j = 0; j < 8; j++) {
            o4[j][0] *= sc0; o4[j][1] *= sc0;
            o4[j][2] *= sc1; o4[j][3] *= sc1;
        }
        m0 = mn0; m1 = mn1;
#pragma unroll
        for (int j = 0; j < 8; j++) {
            float p0 = __expf(s4[j][0] - m0);
            float p1 = __expf(s4[j][1] - m0);
            float p2 = __expf(s4[j][2] - m1);
            float p3 = __expf(s4[j][3] - m1);
            l0 += p0 + p1; l1 += p2 + p3;
            s4[j][0] = p0; s4[j][1] = p1; s4[j][2] = p2; s4[j][3] = p3;
        }
        // ---- P -> A fragments (hi/lo) ----
        uint32_t pfh[4][4], pfl[4][4];
#pragma unroll
        for (int ks = 0; ks < 4; ks++) {
            float v00 = s4[2 * ks][0],     v01 = s4[2 * ks][1];
            float v10 = s4[2 * ks][2],     v11 = s4[2 * ks][3];
            float v20 = s4[2 * ks + 1][0], v21 = s4[2 * ks + 1][1];
            float v30 = s4[2 * ks + 1][2], v31 = s4[2 * ks + 1][3];
            __nv_bfloat162 h0 = __floats2bfloat162_rn(v00, v01);
            __nv_bfloat162 h1 = __floats2bfloat162_rn(v10, v11);
            __nv_bfloat162 h2 = __floats2bfloat162_rn(v20, v21);
            __nv_bfloat162 h3 = __floats2bfloat162_rn(v30, v31);
            float2 f0 = __bfloat1622float2(h0), f1 = __bfloat1622float2(h1);
            float2 f2 = __bfloat1622float2(h2), f3 = __bfloat1622float2(h3);
            pfh[ks][0] = *reinterpret_cast<uint32_t*>(&h0);
            pfh[ks][1] = *reinterpret_cast<uint32_t*>(&h1);
            pfh[ks][2] = *reinterpret_cast<uint32_t*>(&h2);
            pfh[ks][3] = *reinterpret_cast<uint32_t*>(&h3);
            pfl[ks][0] = packbf2(v00 - f0.x, v01 - f0.y);
            pfl[ks][1] = packbf2(v10 - f1.x, v11 - f1.y);
            pfl[ks][2] = packbf2(v20 - f2.x, v21 - f2.y);
            pfl[ks][3] = packbf2(v30 - f3.x, v31 - f3.y);
        }
        // ---- O += P V (bf16x3) ----
#pragma unroll
        for (int ks = 0; ks < 4; ks++) {
            uint32_t x = (uint32_t)(ks * 32);
            uint32_t vh[4][4], vl[4][4];
#pragma unroll
            for (int j = 0; j < 4; j++) {
                ldx4(vh[j][0], vh[j][1], vh[j][2], vh[j][3], (kvb + 16384 + bOff[j]) ^ x);
                ldx4(vl[j][0], vl[j][1], vl[j][2], vl[j][3], (kvb + 24576 + bOff[j]) ^ x);
            }
#pragma unroll
            for (int j = 0; j < 4; j++) {
                mma16816(o4[2 * j],     pfh[ks][0], pfh[ks][1], pfh[ks][2], pfh[ks][3], vh[j][0], vh[j][1]);
                mma16816(o4[2 * j + 1], pfh[ks][0], pfh[ks][1], pfh[ks][2], pfh[ks][3], vh[j][2], vh[j][3]);
                mma16816(o4[2 * j],     pfh[ks][0], pfh[ks][1], pfh[ks][2], pfh[ks][3], vl[j][0], vl[j][1]);
                mma16816(o4[2 * j + 1], pfh[ks][0], pfh[ks][1], pfh[ks][2], pfh[ks][3], vl[j][2], vl[j][3]);
                mma16816(o4[2 * j],     pfl[ks][0], pfl[ks][1], pfl[ks][2], pfl[ks][3], vh[j][0], vh[j][1]);
                mma16816(o4[2 * j + 1], pfl[ks][0], pfl[ks][1], pfl[ks][2], pfl[ks][3], vh[j][2], vh[j][3]);
            }
        }

        __syncthreads();
        // refill stage s with chunk c+2
        if (c + 2 <= 5) {
            int kb2 = start + (c + 2) * 64;
            uint32_t base2 = sb + 32768 + (uint32_t)s * 32768;
#pragma unroll
            for (int i = 0; i < 2; i++) {
                int slot = tid * 2 + i;
                int row = slot >> 3, ch = slot & 7;
                uint32_t d = swz64(row, ch);
                cpasync16(base2 + d,         g_kh + (size_t)(kb2 + row) * 512 + h * 64 + ch * 8);
                cpasync16(base2 + 8192 + d,  g_kl + (size_t)(kb2 + row) * 512 + h * 64 + ch * 8);
                cpasync16(base2 + 16384 + d, g_vth + (size_t)(h * 64 + row) * NTOK + kb2 + ch * 8);
                cpasync16(base2 + 24576 + d, g_vtl + (size_t)(h * 64 + row) * NTOK + kb2 + ch * 8);
            }
            CP_COMMIT();
        }
    }

    // ---- epilogue: normalize, split, store ----
    l0 += __shfl_xor_sync(0xFFFFFFFF, l0, 1);
    l0 += __shfl_xor_sync(0xFFFFFFFF, l0, 2);
    l1 += __shfl_xor_sync(0xFFFFFFFF, l1, 1);
    l1 += __shfl_xor_sync(0xFFFFFFFF, l1, 2);
    float il0 = 1.f / l0, il1 = 1.f / l1;

#pragma unroll
    for (int j = 0; j < 8; j++) {
        int col = h * 64 + j * 8 + colq;
        size_t off0 = (size_t)r0 * 512 + col;
        size_t off1 = (size_t)(r0 + 8) * 512 + col;
        float v0 = o4[j][0] * il0, v1 = o4[j][1] * il0;
        float v2 = o4[j][2] * il1, v3 = o4[j][3] * il1;
        __nv_bfloat162 h0 = __floats2bfloat162_rn(v0, v1);
        __nv_bfloat162 h1 = __floats2bfloat162_rn(v2, v3);
        float2 f0 = __bfloat1622float2(h0), f1 = __bfloat1622float2(h1);
        *(__nv_bfloat162*)(g_ah + off0) = h0;
        *(__nv_bfloat162*)(g_al + off0) = __floats2bfloat162_rn(v0 - f0.x, v1 - f0.y);
        *(__nv_bfloat162*)(g_ah + off1) = h1;
        *(__nv_bfloat162*)(g_al + off1) = __floats2bfloat162_rn(v2 - f1.x, v3 - f1.y);
    }
}

// ---------------------------------------------------------------------------
__global__ void glu_kernel()
{
    int idx = blockIdx.x * blockDim.x + threadIdx.x;
    if (idx >= NTOK * FFPAD) return;
    int r = idx / FFPAD;
    int jc = idx - r * FFPAD;
    float v = 0.f;
    if (jc < FF) {
        float a = g_h[(size_t)r * FF2 + jc];
        float g = g_h[(size_t)r * FF2 + FF + jc];
        v = a * 0.5f * g * (1.f + erff(g * 0.70710678118654752f));
    }
    __nv_bfloat16 hv = __float2bfloat16(v);
    g_gh[idx] = hv;
    g_gl[idx] = __float2bfloat16(v - __bfloat162float(hv));
}

// ---------------------------------------------------------------------------
extern "C" void kernel_launch(void* const* d_in, const int* in_sizes, int n_in,
                              void* d_out, int out_size)
{
    const float* x      = (const float*)d_in[0];
    const float* Wqkv   = (const float*)d_in[1];
    const float* Wo     = (const float*)d_in[2];
    const float* qscale = (const float*)d_in[3];
    const float* kscale = (const float*)d_in[4];
    const float* W1     = (const float*)d_in[5];
    const float* b1     = (const float*)d_in[6];
    const float* W2     = (const float*)d_in[7];
    const float* b2     = (const float*)d_in[8];

    float *px, *pqkv, *ph;
    __nv_bfloat16 *pah, *pal, *pa2h, *pa2l, *pgh, *pgl, *pbh, *pbl;
    cudaGetSymbolAddress((void**)&px, g_x);
    cudaGetSymbolAddress((void**)&pqkv, g_qkv);
    cudaGetSymbolAddress((void**)&ph, g_h);
    cudaGetSymbolAddress((void**)&pah, g_ah);
    cudaGetSymbolAddress((void**)&pal, g_al);
    cudaGetSymbolAddress((void**)&pa2h, g_a2h);
    cudaGetSymbolAddress((void**)&pa2l, g_a2l);
    cudaGetSymbolAddress((void**)&pgh, g_gh);
    cudaGetSymbolAddress((void**)&pgl, g_gl);
    cudaGetSymbolAddress((void**)&pbh, g_bh);
    cudaGetSymbolAddress((void**)&pbl, g_bl);

    cudaFuncSetAttribute(bf16_gemm_kernel,
                         cudaFuncAttributeMaxDynamicSharedMemorySize, GEMM_SMEM);
    cudaFuncSetAttribute(flash_attn_kernel,
                         cudaFuncAttributeMaxDynamicSharedMemorySize, ATT_SMEM);

    split_pad_A<<<(NTOK * 512 + 255) / 256, 256>>>(x, pah, pal, NTOK, DIMM, 512);

    for (int lyr = 0; lyr < DEPTH; lyr++) {
        const float* xres = (lyr == 0) ? x : px;

        // 1) QKV projection
        split_pad_Bt<<<dim3(16, 48), 256>>>(
            Wqkv + (size_t)lyr * DIMM * 3 * INNER, pbh, pbl, DIMM, 3 * INNER, 512, 1536);
        bf16_gemm_kernel<<<dim3(12, 64), 256, GEMM_SMEM>>>(
            pah, pal, pbh, pbl, nullptr, nullptr, pqkv, nullptr, nullptr,
            NTOK, 3 * INNER, 512);

        // 2) qk norm + rope -> bf16 splits; v transpose -> bf16 splits
        qknorm_rope_kernel<<<NTOK, 256>>>(qscale + lyr * DH, kscale + lyr * DH);
        vtrans_kernel<<<dim3(256, 16), 256>>>();

        // 3) flash attention -> g_ah/g_al
        flash_attn_kernel<<<dim3(64, 8), 256, ATT_SMEM>>>();

        // 4) output projection + residual; split-out
        split_pad_Bt<<<dim3(16, 16), 256>>>(
            Wo + (size_t)lyr * INNER * DIMM, pbh, pbl, INNER, DIMM, 512, 512);
        bf16_gemm_kernel<<<dim3(4, 64), 256, GEMM_SMEM>>>(
            pah, pal, pbh, pbl, nullptr, xres, px, pa2h, pa2l,
            NTOK, DIMM, 512);

        // 5) FF up projection + b1
        split_pad_Bt<<<dim3(16, 88), 256>>>(
            W1 + (size_t)lyr * DIMM * FF2, pbh, pbl, DIMM, FF2, 512, FF2SCR);
        bf16_gemm_kernel<<<dim3(22, 64), 256, GEMM_SMEM>>>(
            pa2h, pa2l, pbh, pbl, b1 + (size_t)lyr * FF2, nullptr, ph, nullptr, nullptr,
            NTOK, FF2, 512);

        // 6) gated GELU
        glu_kernel<<<(NTOK * FFPAD + 255) / 256, 256>>>();

        // 7) FF down projection + b2 + residual
        split_pad_Bt<<<dim3(43, 16), 256>>>(
            W2 + (size_t)lyr * FF * DIMM, pbh, pbl, FF, DIMM, FFPAD, 512);
        float* outp = (lyr == DEPTH - 1) ? (float*)d_out : px;
        __nv_bfloat16* oh = (lyr == DEPTH - 1) ? nullptr : pah;
        __nv_bfloat16* ol = (lyr == DEPTH - 1) ? nullptr : pal;
        bf16_gemm_kernel<<<dim3(4, 64), 256, GEMM_SMEM>>>(
            pgh, pgl, pbh, pbl, b2 + (size_t)lyr * DIMM, px, outp, oh, ol,
            NTOK, DIMM, FFPAD);
    }
}

// round 8
// speedup vs baseline: 2.1654x; 1.0148x over previous
#include <cuda_runtime.h>
#include <cuda_bf16.h>
#include <cstdint>
#include <cfloat>
#include <math.h>

#define NTOK 8192
#define DIMM 512
#define DEPTH 6
#define HEADS 8
#define DH 64
#define WSZ 256
#define INNER 512
#define FF 1365
#define FF2 2730
#define FFPAD 1408          // = 2816/2, padded pair count
#define FF2SCR 2816

// ---------------------------------------------------------------------------
// Scratch (device globals; allocation is banned)
// ---------------------------------------------------------------------------
__device__ __align__(256) float g_x[NTOK * DIMM];
__device__ __align__(256) float g_qkv[NTOK * 3 * INNER];
__device__ __align__(256) float g_pb1[FF2SCR];
__device__ __align__(256) __nv_bfloat16 g_ah[NTOK * 512],  g_al[NTOK * 512];
__device__ __align__(256) __nv_bfloat16 g_a2h[NTOK * 512], g_a2l[NTOK * 512];
__device__ __align__(256) __nv_bfloat16 g_gh[(size_t)NTOK * FFPAD], g_gl[(size_t)NTOK * FFPAD];
__device__ __align__(256) __nv_bfloat16 g_bh[2880 * 1024], g_bl[2880 * 1024];
// attention operand splits
__device__ __align__(256) __nv_bfloat16 g_qh[NTOK * 512], g_ql[NTOK * 512];
__device__ __align__(256) __nv_bfloat16 g_kh[NTOK * 512], g_kl[NTOK * 512];
__device__ __align__(256) __nv_bfloat16 g_vth[512 * NTOK], g_vtl[512 * NTOK];

__device__ __forceinline__ uint32_t smem_to_u32(const void* p) {
    uint32_t a;
    asm("{ .reg .u64 t; cvta.to.shared.u64 t, %1; cvt.u32.u64 %0, t; }" : "=r"(a) : "l"(p));
    return a;
}
__device__ __forceinline__ void cpasync16(uint32_t dst, const void* src) {
    asm volatile("cp.async.cg.shared.global [%0], [%1], 16;" :: "r"(dst), "l"(src) : "memory");
}
#define CP_COMMIT() asm volatile("cp.async.commit_group;" ::: "memory")
#define CP_WAIT(n) asm volatile("cp.async.wait_group %0;" :: "n"(n) : "memory")

// GEMM tile swizzle: [128 rows][32 k] bf16, 2 logical rows per 128B row.
__device__ __forceinline__ uint32_t swz(int r, int chunk) {
    int pr = r >> 1;
    int cc = ((r & 1) << 2) | chunk;
    cc ^= (pr & 7);
    return (uint32_t)(pr * 128 + cc * 16);
}
// Attention tile swizzle: [rows][64 bf16] = 128B per row.
__device__ __forceinline__ uint32_t swz64(int r, int c) {
    return (uint32_t)(r * 128 + ((c ^ (r & 7)) * 16));
}

__device__ __forceinline__ void ldx4(uint32_t& d0, uint32_t& d1, uint32_t& d2, uint32_t& d3,
                                     uint32_t addr) {
    asm volatile("ldmatrix.sync.aligned.m8n8.x4.shared.b16 {%0,%1,%2,%3}, [%4];"
                 : "=r"(d0), "=r"(d1), "=r"(d2), "=r"(d3) : "r"(addr));
}
__device__ __forceinline__ void mma16816(float* c, uint32_t a0, uint32_t a1, uint32_t a2,
                                         uint32_t a3, uint32_t b0, uint32_t b1) {
    asm volatile(
        "mma.sync.aligned.m16n8k16.row.col.f32.bf16.bf16.f32 "
        "{%0,%1,%2,%3}, {%4,%5,%6,%7}, {%8,%9}, {%0,%1,%2,%3};"
        : "+f"(c[0]), "+f"(c[1]), "+f"(c[2]), "+f"(c[3])
        : "r"(a0), "r"(a1), "r"(a2), "r"(a3), "r"(b0), "r"(b1));
}
__device__ __forceinline__ uint32_t packbf2(float a, float b) {
    __nv_bfloat162 h = __floats2bfloat162_rn(a, b);
    return *reinterpret_cast<uint32_t*>(&h);
}

// ===========================================================================
// Conversion kernels
// ===========================================================================
__global__ void split_pad_A(const float* __restrict__ src,
                            __nv_bfloat16* __restrict__ h, __nv_bfloat16* __restrict__ l,
                            int Mr, int Kc, int Kp)
{
    int idx = blockIdx.x * 256 + threadIdx.x;
    if (idx >= Mr * Kp) return;
    int r = idx / Kp, c = idx - r * Kp;
    float v = (c < Kc) ? src[(size_t)r * Kc + c] : 0.f;
    __nv_bfloat16 hv = __float2bfloat16(v);
    h[idx] = hv;
    l[idx] = __float2bfloat16(v - __bfloat162float(hv));
}

// Weight [Kc][srcStride] -> transposed, padded splits [Nscr][Kp] (32x32 tiles).
// gluPerm: output row n takes source col (n&1) ? n/2 + FF : n/2 (GLU pair interleave).
__global__ void split_pad_Bt(const float* __restrict__ src,
                             __nv_bfloat16* __restrict__ h, __nv_bfloat16* __restrict__ l,
                             int Kc, int Nc, int Kp, int Nscr, int srcStride, int gluPerm)
{
    __shared__ float t[32][33];
    int tk0 = blockIdx.x * 32;
    int tn0 = blockIdx.y * 32;
    int tx = threadIdx.x & 31;
    int ty = threadIdx.x >> 5;

    int nout = tn0 + tx;
    int ns; bool nok;
    if (gluPerm) {
        int p = nout >> 1;
        ns = (nout & 1) ? p + FF : p;
        nok = p < FF;
    } else {
        ns = nout;
        nok = nout < Nc;
    }
#pragma unroll
    for (int i = 0; i < 4; i++) {
        int k = tk0 + ty + 8 * i;
        float v = (k < Kc && nok) ? src[(size_t)k * srcStride + ns] : 0.f;
        t[ty + 8 * i][tx] = v;
    }
    __syncthreads();
#pragma unroll
    for (int i = 0; i < 4; i++) {
        int n = tn0 + ty + 8 * i, k = tk0 + tx;
        if (n < Nscr && k < Kp) {
            float v = t[tx][ty + 8 * i];
            __nv_bfloat16 hv = __float2bfloat16(v);
            size_t o = (size_t)n * Kp + k;
            h[o] = hv;
            l[o] = __float2bfloat16(v - __bfloat162float(hv));
        }
    }
}

// permute b1 into GLU-pair order
__global__ void permute_b1_kernel(const float* __restrict__ b1)
{
    int n = blockIdx.x * 256 + threadIdx.x;
    if (n >= FF2SCR) return;
    int p = n >> 1;
    g_pb1[n] = (p < FF) ? b1[(n & 1) ? p + FF : p] : 0.f;
}

// V transpose+split: g_qkv v-part [tok][hd] -> g_vth/g_vtl [hd][tok]
__global__ void vtrans_kernel()
{
    __shared__ float t[32][33];
    int tok0 = blockIdx.x * 32;
    int hd0 = blockIdx.y * 32;
    int tx = threadIdx.x & 31;
    int ty = threadIdx.x >> 5;
#pragma unroll
    for (int i = 0; i < 4; i++) {
        int tok = tok0 + ty + 8 * i;
        t[ty + 8 * i][tx] = g_qkv[(size_t)tok * 1536 + 1024 + hd0 + tx];
    }
    __syncthreads();
#pragma unroll
    for (int i = 0; i < 4; i++) {
        int hd = hd0 + ty + 8 * i, tok = tok0 + tx;
        float v = t[tx][ty + 8 * i];
        __nv_bfloat16 hv = __float2bfloat16(v);
        size_t o = (size_t)hd * NTOK + tok;
        g_vth[o] = hv;
        g_vtl[o] = __float2bfloat16(v - __bfloat162float(hv));
    }
}

// ===========================================================================
// Pure-bf16 tensor-core GEMM, single-sync 3-stage pipeline.
// glu mode: epilogue computes a*gelu(g) on column pairs, emits splits only.
// ===========================================================================
#define STAGE_BYTES 32768
#define NSTAGE 3
#define GEMM_SMEM (NSTAGE * STAGE_BYTES + 1024)

__global__ void __launch_bounds__(256, 2) bf16_gemm_kernel(
    const __nv_bfloat16* __restrict__ Ah, const __nv_bfloat16* __restrict__ Al,
    const __nv_bfloat16* __restrict__ Bh, const __nv_bfloat16* __restrict__ Bl,
    const float* __restrict__ bias, const float* __restrict__ res,
    float* __restrict__ C, __nv_bfloat16* __restrict__ Oh, __nv_bfloat16* __restrict__ Ol,
    int M, int N, int Kpad, int ostride, int glu)
{
    extern __shared__ char smraw[];
    char* sm = (char*)(((uintptr_t)smraw + 1023) & ~(uintptr_t)1023);
    uint32_t sb = smem_to_u32(sm);

    int tid = threadIdx.x, wid = tid >> 5, lane = tid & 31;
    int mw = wid >> 1, nw = wid & 1;
    int m0 = blockIdx.y * 128, n0 = blockIdx.x * 128;

    uint32_t aAddr[2], bAddr[4];
    {
        int t = lane >> 3, l7 = lane & 7;
#pragma unroll
        for (int mi = 0; mi < 2; mi++) {
            int r = mw * 32 + mi * 16 + ((t & 1) << 3) + l7;
            aAddr[mi] = sb + swz(r, t >> 1);
        }
#pragma unroll
        for (int j = 0; j < 4; j++) {
            int r = nw * 64 + j * 16 + ((t >> 1) << 3) + l7;
            bAddr[j] = sb + 16384 + swz(r, t & 1);
        }
    }

    float acc[2][8][4];
#pragma unroll
    for (int mi = 0; mi < 2; mi++)
#pragma unroll
        for (int j = 0; j < 8; j++)
#pragma unroll
            for (int q = 0; q < 4; q++) acc[mi][j][q] = 0.f;

    const int niter = Kpad / 32;
    int cr = tid >> 1;
    int c0 = (tid & 1) * 2;
    const __nv_bfloat16* aSrcH = Ah + (size_t)(m0 + cr) * Kpad + c0 * 8;
    const __nv_bfloat16* aSrcL = Al + (size_t)(m0 + cr) * Kpad + c0 * 8;
    const __nv_bfloat16* bSrcH = Bh + (size_t)(n0 + cr) * Kpad + c0 * 8;
    const __nv_bfloat16* bSrcL = Bl + (size_t)(n0 + cr) * Kpad + c0 * 8;
    uint32_t dA0 = swz(cr, c0), dA1 = swz(cr, c0 + 1);

#define ISSUE_STAGE(s, k0) do {                                           \
        uint32_t base = sb + (uint32_t)(s) * STAGE_BYTES;                 \
        cpasync16(base + dA0,         aSrcH + (k0));                      \
        cpasync16(base + dA1,         aSrcH + (k0) + 8);                  \
        cpasync16(base + 8192 + dA0,  aSrcL + (k0));                      \
        cpasync16(base + 8192 + dA1,  aSrcL + (k0) + 8);                  \
        cpasync16(base + 16384 + dA0, bSrcH + (k0));                      \
        cpasync16(base + 16384 + dA1, bSrcH + (k0) + 8);                  \
        cpasync16(base + 24576 + dA0, bSrcL + (k0));                      \
        cpasync16(base + 24576 + dA1, bSrcL + (k0) + 8);                  \
        CP_COMMIT();                                                      \
    } while (0)

    ISSUE_STAGE(0, 0);
    if (niter > 1) ISSUE_STAGE(1, 32);

    for (int it = 0; it < niter; ++it) {
        int s = it % NSTAGE;
        if (it + 1 < niter) CP_WAIT(1); else CP_WAIT(0);
        __syncthreads();
        if (it + 2 < niter) ISSUE_STAGE((it + 2) % NSTAGE, (it + 2) * 32);

        uint32_t stage = (uint32_t)s * STAGE_BYTES;
#pragma unroll
        for (int kk = 0; kk < 2; kk++) {
            uint32_t x = (uint32_t)(kk * 32);
            uint32_t a0A = (aAddr[0] + stage) ^ x;
            uint32_t a1A = (aAddr[1] + stage) ^ x;
            uint32_t ah[2][4], bh[4][4];
            ldx4(ah[0][0], ah[0][1], ah[0][2], ah[0][3], a0A);
            ldx4(ah[1][0], ah[1][1], ah[1][2], ah[1][3], a1A);
#pragma unroll
            for (int j = 0; j < 4; j++) {
                uint32_t bA = (bAddr[j] + stage) ^ x;
                ldx4(bh[j][0], bh[j][1], bh[j][2], bh[j][3], bA);
            }
#pragma unroll
            for (int mi = 0; mi < 2; mi++)
#pragma unroll
                for (int j = 0; j < 4; j++) {
                    mma16816(acc[mi][2 * j],     ah[mi][0], ah[mi][1], ah[mi][2], ah[mi][3], bh[j][0], bh[j][1]);
                    mma16816(acc[mi][2 * j + 1], ah[mi][0], ah[mi][1], ah[mi][2], ah[mi][3], bh[j][2], bh[j][3]);
                }
#pragma unroll
            for (int j = 0; j < 4; j++) {
                uint32_t bl[4];
                ldx4(bl[0], bl[1], bl[2], bl[3], ((bAddr[j] + stage) ^ x) + 8192);
#pragma unroll
                for (int mi = 0; mi < 2; mi++) {
                    mma16816(acc[mi][2 * j],     ah[mi][0], ah[mi][1], ah[mi][2], ah[mi][3], bl[0], bl[1]);
                    mma16816(acc[mi][2 * j + 1], ah[mi][0], ah[mi][1], ah[mi][2], ah[mi][3], bl[2], bl[3]);
                }
            }
            ldx4(ah[0][0], ah[0][1], ah[0][2], ah[0][3], a0A + 8192);
            ldx4(ah[1][0], ah[1][1], ah[1][2], ah[1][3], a1A + 8192);
#pragma unroll
            for (int mi = 0; mi < 2; mi++)
#pragma unroll
                for (int j = 0; j < 4; j++) {
                    mma16816(acc[mi][2 * j],     ah[mi][0], ah[mi][1], ah[mi][2], ah[mi][3], bh[j][0], bh[j][1]);
                    mma16816(acc[mi][2 * j + 1], ah[mi][0], ah[mi][1], ah[mi][2], ah[mi][3], bh[j][2], bh[j][3]);
                }
        }
    }
#undef ISSUE_STAGE

    // ---- epilogue ----
#pragma unroll
    for (int mi = 0; mi < 2; mi++) {
        int rbase = m0 + mw * 32 + mi * 16 + (lane >> 2);
#pragma unroll
        for (int j = 0; j < 8; j++) {
            int col = n0 + nw * 64 + j * 8 + (lane & 3) * 2;
            if (col < N) {
                float bx = 0.f, by = 0.f;
                if (bias) { bx = bias[col]; by = bias[col + 1]; }
                if (glu) {
                    int p = col >> 1;
#pragma unroll
                    for (int half = 0; half < 2; half++) {
                        int r = rbase + half * 8;
                        float a = acc[mi][j][half * 2] + bx;
                        float g = acc[mi][j][half * 2 + 1] + by;
                        float v = a * 0.5f * g * (1.f + erff(g * 0.70710678118654752f));
                        __nv_bfloat16 hv = __float2bfloat16(v);
                        size_t o = (size_t)r * ostride + p;
                        Oh[o] = hv;
                        Ol[o] = __float2bfloat16(v - __bfloat162float(hv));
                    }
                } else {
#pragma unroll
                    for (int half = 0; half < 2; half++) {
                        int r = rbase + half * 8;
                        size_t o = (size_t)r * N + col;
                        float v0 = acc[mi][j][half * 2] + bx;
                        float v1 = acc[mi][j][half * 2 + 1] + by;
                        if (res) { v0 += res[o]; v1 += res[o + 1]; }
                        *(float2*)(C + o) = make_float2(v0, v1);
                        if (Oh) {
                            size_t oo = (size_t)r * ostride + col;
                            __nv_bfloat162 hv = __floats2bfloat162_rn(v0, v1);
                            float2 hf = __bfloat1622float2(hv);
                            *(__nv_bfloat162*)(Oh + oo) = hv;
                            *(__nv_bfloat162*)(Ol + oo) = __floats2bfloat162_rn(v0 - hf.x, v1 - hf.y);
                        }
                    }
                }
            }
        }
    }
}

// ---------------------------------------------------------------------------
// QK l2-norm + xpos rotary; emits bf16 hi/lo splits of q,k.
// ---------------------------------------------------------------------------
__global__ void qknorm_rope_kernel(const float* __restrict__ qscale,
                                   const float* __restrict__ kscale)
{
    int task = blockIdx.x * 8 + (threadIdx.x >> 5);
    int lane = threadIdx.x & 31;
    int pos = task >> 3;
    int h = task & 7;

    const float* qp = g_qkv + (size_t)pos * (3 * INNER) + h * DH;
    const float* kp = qp + INNER;

    float q0 = qp[lane], q1 = qp[lane + 32];
    float k0 = kp[lane], k1 = kp[lane + 32];

    float sq = q0 * q0 + q1 * q1;
    float sk = k0 * k0 + k1 * k1;
#pragma unroll
    for (int o = 16; o > 0; o >>= 1) {
        sq += __shfl_xor_sync(0xFFFFFFFF, sq, o);
        sk += __shfl_xor_sync(0xFFFFFFFF, sk, o);
    }
    float invq = 1.f / fmaxf(sqrtf(sq), 1e-12f);
    float invk = 1.f / fmaxf(sqrtf(sk), 1e-12f);
    q0 *= invq * qscale[lane];
    q1 *= invq * qscale[lane + 32];
    k0 *= invk * kscale[lane];
    k1 *= invk * kscale[lane + 32];

    float t = (float)pos;
    float inv_freq = powf(10000.f, -(float)lane / 32.f);
    float fr = t * inv_freq;
    float c = cosf(fr), s = sinf(fr);
    float sv = (2.f * (float)lane + 0.4f * 64.f) / (1.4f * 64.f);
    float pw = (t - (float)(NTOK / 2)) / (float)(WSZ / 2);
    float xs = powf(sv, pw);
    float ixs = 1.f / xs;

    float qa = (q0 * c - q1 * s) * xs;
    float qb = (q1 * c + q0 * s) * xs;
    float ka = (k0 * c - k1 * s) * ixs;
    float kb = (k1 * c + k0 * s) * ixs;

    size_t ob = (size_t)pos * 512 + h * DH;
    __nv_bfloat16 hv;
    hv = __float2bfloat16(qa); g_qh[ob + lane] = hv;
    g_ql[ob + lane] = __float2bfloat16(qa - __bfloat162float(hv));
    hv = __float2bfloat16(qb); g_qh[ob + lane + 32] = hv;
    g_ql[ob + lane + 32] = __float2bfloat16(qb - __bfloat162float(hv));
    hv = __float2bfloat16(ka); g_kh[ob + lane] = hv;
    g_kl[ob + lane] = __float2bfloat16(ka - __bfloat162float(hv));
    hv = __float2bfloat16(kb); g_kh[ob + lane + 32] = hv;
    g_kl[ob + lane + 32] = __float2bfloat16(kb - __bfloat162float(hv));
}

// ===========================================================================
// Tensor-core flash attention (validated R7 structure).
// ===========================================================================
#define ATT_SMEM (32768 + 2 * 32768 + 1024)

__global__ void __launch_bounds__(256) flash_attn_kernel()
{
    extern __shared__ char smraw[];
    char* sm = (char*)(((uintptr_t)smraw + 1023) & ~(uintptr_t)1023);
    uint32_t sb = smem_to_u32(sm);

    int tid = threadIdx.x, wid = tid >> 5, lane = tid & 31;
    int qb = blockIdx.x;
    int h = blockIdx.y;
    int start = (qb - 2) * 128;
    int cBeg = (start < 0) ? (-start) / 64 : 0;

    {
#pragma unroll
        for (int i = 0; i < 4; i++) {
            int slot = tid * 4 + i;
            int row = slot >> 3, ch = slot & 7;
            uint32_t d = swz64(row, ch);
            const __nv_bfloat16* sh = g_qh + (size_t)(qb * 128 + row) * 512 + h * 64 + ch * 8;
            const __nv_bfloat16* slo = g_ql + (size_t)(qb * 128 + row) * 512 + h * 64 + ch * 8;
            cpasync16(sb + d, sh);
            cpasync16(sb + 16384 + d, slo);
        }
        int kb = start + cBeg * 64;
        uint32_t base = sb + 32768;
#pragma unroll
        for (int i = 0; i < 2; i++) {
            int slot = tid * 2 + i;
            int row = slot >> 3, ch = slot & 7;
            uint32_t d = swz64(row, ch);
            cpasync16(base + d,         g_kh + (size_t)(kb + row) * 512 + h * 64 + ch * 8);
            cpasync16(base + 8192 + d,  g_kl + (size_t)(kb + row) * 512 + h * 64 + ch * 8);
            cpasync16(base + 16384 + d, g_vth + (size_t)(h * 64 + row) * NTOK + kb + ch * 8);
            cpasync16(base + 24576 + d, g_vtl + (size_t)(h * 64 + row) * NTOK + kb + ch * 8);
        }
        CP_COMMIT();
        if (cBeg + 1 <= 5) {
            int kb2 = start + (cBeg + 1) * 64;
            uint32_t base2 = sb + 32768 + 32768;
#pragma unroll
            for (int i = 0; i < 2; i++) {
                int slot = tid * 2 + i;
                int row = slot >> 3, ch = slot & 7;
                uint32_t d = swz64(row, ch);
                cpasync16(base2 + d,         g_kh + (size_t)(kb2 + row) * 512 + h * 64 + ch * 8);
                cpasync16(base2 + 8192 + d,  g_kl + (size_t)(kb2 + row) * 512 + h * 64 + ch * 8);
                cpasync16(base2 + 16384 + d, g_vth + (size_t)(h * 64 + row) * NTOK + kb2 + ch * 8);
                cpasync16(base2 + 24576 + d, g_vtl + (size_t)(h * 64 + row) * NTOK + kb2 + ch * 8);
            }
            CP_COMMIT();
        }
    }

    int t = lane >> 3, l7 = lane & 7;
    uint32_t aOff = swz64(wid * 16 + ((t & 1) << 3) + l7, t >> 1);
    uint32_t bOff[4];
#pragma unroll
    for (int j = 0; j < 4; j++)
        bOff[j] = swz64(j * 16 + ((t >> 1) << 3) + l7, t & 1);

    uint32_t qfh[4][4], qfl[4][4];
    float o4[8][4];
#pragma unroll
    for (int j = 0; j < 8; j++)
#pragma unroll
        for (int q = 0; q < 4; q++) o4[j][q] = 0.f;
    float m0 = -16.f, m1 = -16.f, l0 = 0.f, l1 = 0.f;

    int r0 = qb * 128 + wid * 16 + (lane >> 2);
    int colq = (lane & 3) * 2;

    for (int c = cBeg; c <= 5; c++) {
        int s = (c - cBeg) & 1;
        int kb = start + c * 64;
        if (c < 5) CP_WAIT(1); else CP_WAIT(0);
        __syncthreads();

        if (c == cBeg) {
#pragma unroll
            for (int ks = 0; ks < 4; ks++) {
                uint32_t x = (uint32_t)(ks * 32);
                ldx4(qfh[ks][0], qfh[ks][1], qfh[ks][2], qfh[ks][3], (sb + aOff) ^ x);
                ldx4(qfl[ks][0], qfl[ks][1], qfl[ks][2], qfl[ks][3], (sb + 16384 + aOff) ^ x);
            }
        }

        uint32_t kvb = sb + 32768 + (uint32_t)s * 32768;

        float s4[8][4];
#pragma unroll
        for (int j = 0; j < 8; j++)
#pragma unroll
            for (int q = 0; q < 4; q++) s4[j][q] = 0.f;

#pragma unroll
        for (int ks = 0; ks < 4; ks++) {
            uint32_t x = (uint32_t)(ks * 32);
            uint32_t bh[4][4], bl[4][4];
#pragma unroll
            for (int j = 0; j < 4; j++) {
                ldx4(bh[j][0], bh[j][1], bh[j][2], bh[j][3], (kvb + bOff[j]) ^ x);
                ldx4(bl[j][0], bl[j][1], bl[j][2], bl[j][3], (kvb + 8192 + bOff[j]) ^ x);
            }
#pragma unroll
            for (int j = 0; j < 4; j++) {
                mma16816(s4[2 * j],     qfh[ks][0], qfh[ks][1], qfh[ks][2], qfh[ks][3], bh[j][0], bh[j][1]);
                mma16816(s4[2 * j + 1], qfh[ks][0], qfh[ks][1], qfh[ks][2], qfh[ks][3], bh[j][2], bh[j][3]);
                mma16816(s4[2 * j],     qfh[ks][0], qfh[ks][1], qfh[ks][2], qfh[ks][3], bl[j][0], bl[j][1]);
                mma16816(s4[2 * j + 1], qfh[ks][0], qfh[ks][1], qfh[ks][2], qfh[ks][3], bl[j][2], bl[j][3]);
                mma16816(s4[2 * j],     qfl[ks][0], qfl[ks][1], qfl[ks][2], qfl[ks][3], bh[j][0], bh[j][1]);
                mma16816(s4[2 * j + 1], qfl[ks][0], qfl[ks][1], qfl[ks][2], qfl[ks][3], bh[j][2], bh[j][3]);
            }
        }

#pragma unroll
        for (int j = 0; j < 8; j++) {
            int tkb = kb + j * 8 + colq;
#pragma unroll
            for (int q = 0; q < 4; q++) {
                int tq = r0 + ((q >> 1) << 3);
                int tk = tkb + (q & 1);
                int diff = tq - tk;
                s4[j][q] = (diff >= 0 && diff <= WSZ) ? s4[j][q] * 8.0f : -1e30f;
            }
        }
        float mx0 = -1e30f, mx1 = -1e30f;
#pragma unroll
        for (int j = 0; j < 8; j++) {
            mx0 = fmaxf(mx0, fmaxf(s4[j][0], s4[j][1]));
            mx1 = fmaxf(mx1, fmaxf(s4[j][2], s4[j][3]));
        }
        mx0 = fmaxf(mx0, __shfl_xor_sync(0xFFFFFFFF, mx0, 1));
        mx0 = fmaxf(mx0, __shfl_xor_sync(0xFFFFFFFF, mx0, 2));
        mx1 = fmaxf(mx1, __shfl_xor_sync(0xFFFFFFFF, mx1, 1));
        mx1 = fmaxf(mx1, __shfl_xor_sync(0xFFFFFFFF, mx1, 2));
        float mn0 = fmaxf(m0, mx0), mn1 = fmaxf(m1, mx1);
        float sc0 = __expf(m0 - mn0), sc1 = __expf(m1 - mn1);
        l0 *= sc0; l1 *= sc1;
#pragma unroll
        for (int j = 0; j < 8; j++) {
            o4[j][0] *= sc0; o4[j][1] *= sc0;
            o4[j][2] *= sc1; o4[j][3] *= sc1;
        }
        m0 = mn0; m1 = mn1;
#pragma unroll
        for (int j = 0; j < 8; j++) {
            float p0 = __expf(s4[j][0] - m0);
            float p1 = __expf(s4[j][1] - m0);
            float p2 = __expf(s4[j][2] - m1);
            float p3 = __expf(s4[j][3] - m1);
            l0 += p0 + p1; l1 += p2 + p3;
            s4[j][0] = p0; s4[j][1] = p1; s4[j][2] = p2; s4[j][3] = p3;
        }
        uint32_t pfh[4][4], pfl[4][4];
#pragma unroll
        for (int ks = 0; ks < 4; ks++) {
            float v00 = s4[2 * ks][0],     v01 = s4[2 * ks][1];
            float v10 = s4[2 * ks][2],     v11 = s4[2 * ks][3];
            float v20 = s4[2 * ks + 1][0], v21 = s4[2 * ks + 1][1];
            float v30 = s4[2 * ks + 1][2], v31 = s4[2 * ks + 1][3];
            __nv_bfloat162 h0 = __floats2bfloat162_rn(v00, v01);
            __nv_bfloat162 h1 = __floats2bfloat162_rn(v10, v11);
            __nv_bfloat162 h2 = __floats2bfloat162_rn(v20, v21);
            __nv_bfloat162 h3 = __floats2bfloat162_rn(v30, v31);
            float2 f0 = __bfloat1622float2(h0), f1 = __bfloat1622float2(h1);
            float2 f2 = __bfloat1622float2(h2), f3 = __bfloat1622float2(h3);
            pfh[ks][0] = *reinterpret_cast<uint32_t*>(&h0);
            pfh[ks][1] = *reinterpret_cast<uint32_t*>(&h1);
            pfh[ks][2] = *reinterpret_cast<uint32_t*>(&h2);
            pfh[ks][3] = *reinterpret_cast<uint32_t*>(&h3);
            pfl[ks][0] = packbf2(v00 - f0.x, v01 - f0.y);
            pfl[ks][1] = packbf2(v10 - f1.x, v11 - f1.y);
            pfl[ks][2] = packbf2(v20 - f2.x, v21 - f2.y);
            pfl[ks][3] = packbf2(v30 - f3.x, v31 - f3.y);
        }
#pragma unroll
        for (int ks = 0; ks < 4; ks++) {
            uint32_t x = (uint32_t)(ks * 32);
            uint32_t vh[4][4], vl[4][4];
#pragma unroll
            for (int j = 0; j < 4; j++) {
                ldx4(vh[j][0], vh[j][1], vh[j][2], vh[j][3], (kvb + 16384 + bOff[j]) ^ x);
                ldx4(vl[j][0], vl[j][1], vl[j][2], vl[j][3], (kvb + 24576 + bOff[j]) ^ x);
            }
#pragma unroll
            for (int j = 0; j < 4; j++) {
                mma16816(o4[2 * j],     pfh[ks][0], pfh[ks][1], pfh[ks][2], pfh[ks][3], vh[j][0], vh[j][1]);
                mma16816(o4[2 * j + 1], pfh[ks][0], pfh[ks][1], pfh[ks][2], pfh[ks][3], vh[j][2], vh[j][3]);
                mma16816(o4[2 * j],     pfh[ks][0], pfh[ks][1], pfh[ks][2], pfh[ks][3], vl[j][0], vl[j][1]);
                mma16816(o4[2 * j + 1], pfh[ks][0], pfh[ks][1], pfh[ks][2], pfh[ks][3], vl[j][2], vl[j][3]);
                mma16816(o4[2 * j],     pfl[ks][0], pfl[ks][1], pfl[ks][2], pfl[ks][3], vh[j][0], vh[j][1]);
                mma16816(o4[2 * j + 1], pfl[ks][0], pfl[ks][1], pfl[ks][2], pfl[ks][3], vh[j][2], vh[j][3]);
            }
        }

        __syncthreads();
        if (c + 2 <= 5) {
            int kb2 = start + (c + 2) * 64;
            uint32_t base2 = sb + 32768 + (uint32_t)s * 32768;
#pragma unroll
            for (int i = 0; i < 2; i++) {
                int slot = tid * 2 + i;
                int row = slot >> 3, ch = slot & 7;
                uint32_t d = swz64(row, ch);
                cpasync16(base2 + d,         g_kh + (size_t)(kb2 + row) * 512 + h * 64 + ch * 8);
                cpasync16(base2 + 8192 + d,  g_kl + (size_t)(kb2 + row) * 512 + h * 64 + ch * 8);
                cpasync16(base2 + 16384 + d, g_vth + (size_t)(h * 64 + row) * NTOK + kb2 + ch * 8);
                cpasync16(base2 + 24576 + d, g_vtl + (size_t)(h * 64 + row) * NTOK + kb2 + ch * 8);
            }
            CP_COMMIT();
        }
    }

    l0 += __shfl_xor_sync(0xFFFFFFFF, l0, 1);
    l0 += __shfl_xor_sync(0xFFFFFFFF, l0, 2);
    l1 += __shfl_xor_sync(0xFFFFFFFF, l1, 1);
    l1 += __shfl_xor_sync(0xFFFFFFFF, l1, 2);
    float il0 = 1.f / l0, il1 = 1.f / l1;

#pragma unroll
    for (int j = 0; j < 8; j++) {
        int col = h * 64 + j * 8 + colq;
        size_t off0 = (size_t)r0 * 512 + col;
        size_t off1 = (size_t)(r0 + 8) * 512 + col;
        float v0 = o4[j][0] * il0, v1 = o4[j][1] * il0;
        float v2 = o4[j][2] * il1, v3 = o4[j][3] * il1;
        __nv_bfloat162 h0 = __floats2bfloat162_rn(v0, v1);
        __nv_bfloat162 h1 = __floats2bfloat162_rn(v2, v3);
        float2 f0 = __bfloat1622float2(h0), f1 = __bfloat1622float2(h1);
        *(__nv_bfloat162*)(g_ah + off0) = h0;
        *(__nv_bfloat162*)(g_al + off0) = __floats2bfloat162_rn(v0 - f0.x, v1 - f0.y);
        *(__nv_bfloat162*)(g_ah + off1) = h1;
        *(__nv_bfloat162*)(g_al + off1) = __floats2bfloat162_rn(v2 - f1.x, v3 - f1.y);
    }
}

// ---------------------------------------------------------------------------
extern "C" void kernel_launch(void* const* d_in, const int* in_sizes, int n_in,
                              void* d_out, int out_size)
{
    const float* x      = (const float*)d_in[0];
    const float* Wqkv   = (const float*)d_in[1];
    const float* Wo     = (const float*)d_in[2];
    const float* qscale = (const float*)d_in[3];
    const float* kscale = (const float*)d_in[4];
    const float* W1     = (const float*)d_in[5];
    const float* b1     = (const float*)d_in[6];
    const float* W2     = (const float*)d_in[7];
    const float* b2     = (const float*)d_in[8];

    float *px, *pqkv, *ppb1;
    __nv_bfloat16 *pah, *pal, *pa2h, *pa2l, *pgh, *pgl, *pbh, *pbl;
    cudaGetSymbolAddress((void**)&px, g_x);
    cudaGetSymbolAddress((void**)&pqkv, g_qkv);
    cudaGetSymbolAddress((void**)&ppb1, g_pb1);
    cudaGetSymbolAddress((void**)&pah, g_ah);
    cudaGetSymbolAddress((void**)&pal, g_al);
    cudaGetSymbolAddress((void**)&pa2h, g_a2h);
    cudaGetSymbolAddress((void**)&pa2l, g_a2l);
    cudaGetSymbolAddress((void**)&pgh, g_gh);
    cudaGetSymbolAddress((void**)&pgl, g_gl);
    cudaGetSymbolAddress((void**)&pbh, g_bh);
    cudaGetSymbolAddress((void**)&pbl, g_bl);

    cudaFuncSetAttribute(bf16_gemm_kernel,
                         cudaFuncAttributeMaxDynamicSharedMemorySize, GEMM_SMEM);
    cudaFuncSetAttribute(flash_attn_kernel,
                         cudaFuncAttributeMaxDynamicSharedMemorySize, ATT_SMEM);

    split_pad_A<<<(NTOK * 512 + 255) / 256, 256>>>(x, pah, pal, NTOK, DIMM, 512);

    for (int lyr = 0; lyr < DEPTH; lyr++) {
        const float* xres = (lyr == 0) ? x : px;

        // 1) QKV projection
        split_pad_Bt<<<dim3(16, 48), 256>>>(
            Wqkv + (size_t)lyr * DIMM * 3 * INNER, pbh, pbl,
            DIMM, 3 * INNER, 512, 1536, 3 * INNER, 0);
        bf16_gemm_kernel<<<dim3(12, 64), 256, GEMM_SMEM>>>(
            pah, pal, pbh, pbl, nullptr, nullptr, pqkv, nullptr, nullptr,
            NTOK, 3 * INNER, 512, 3 * INNER, 0);

        // 2) qk norm + rope; v transpose
        qknorm_rope_kernel<<<NTOK, 256>>>(qscale + lyr * DH, kscale + lyr * DH);
        vtrans_kernel<<<dim3(256, 16), 256>>>();

        // 3) flash attention -> g_ah/g_al
        flash_attn_kernel<<<dim3(64, 8), 256, ATT_SMEM>>>();

        // 4) output projection + residual; split-out
        split_pad_Bt<<<dim3(16, 16), 256>>>(
            Wo + (size_t)lyr * INNER * DIMM, pbh, pbl,
            INNER, DIMM, 512, 512, DIMM, 0);
        bf16_gemm_kernel<<<dim3(4, 64), 256, GEMM_SMEM>>>(
            pah, pal, pbh, pbl, nullptr, xres, px, pa2h, pa2l,
            NTOK, DIMM, 512, DIMM, 0);

        // 5) FF up projection + b1 + fused GLU (column-pair permuted W1)
        split_pad_Bt<<<dim3(16, 88), 256>>>(
            W1 + (size_t)lyr * DIMM * FF2, pbh, pbl,
            DIMM, FF2SCR, 512, FF2SCR, FF2, 1);
        permute_b1_kernel<<<(FF2SCR + 255) / 256, 256>>>(b1 + (size_t)lyr * FF2);
        bf16_gemm_kernel<<<dim3(22, 64), 256, GEMM_SMEM>>>(
            pa2h, pa2l, pbh, pbl, ppb1, nullptr, nullptr, pgh, pgl,
            NTOK, FF2SCR, 512, FFPAD, 1);

        // 6) FF down projection + b2 + residual
        split_pad_Bt<<<dim3(44, 16), 256>>>(
            W2 + (size_t)lyr * FF * DIMM, pbh, pbl,
            FF, DIMM, FFPAD, 512, DIMM, 0);
        float* outp = (lyr == DEPTH - 1) ? (float*)d_out : px;
        __nv_bfloat16* oh = (lyr == DEPTH - 1) ? nullptr : pah;
        __nv_bfloat16* ol = (lyr == DEPTH - 1) ? nullptr : pal;
        bf16_gemm_kernel<<<dim3(4, 64), 256, GEMM_SMEM>>>(
            pgh, pgl, pbh, pbl, b2 + (size_t)lyr * DIMM, px, outp, oh, ol,
            NTOK, DIMM, FFPAD, DIMM, 0);
    }
}